// round 8
// baseline (speedup 1.0000x reference)
#include <cuda_runtime.h>
#include <cuda_bf16.h>
#include <cstdint>

#define S_LEN  2048
#define DMODEL 1024
#define NHEAD  16
#define HDIM   64
#define MROWS  4096   // S*B
#define NPAIRS 32     // B*NHEAD
#define NX     ((size_t)MROWS * DMODEL)
#define NW     ((size_t)DMODEL * DMODEL)

// ---------------- scratch globals (allocation-free rule) ----------------
__device__ __nv_bfloat16 g_hiX[(size_t)3 * NX];    // converted q/k/v inputs
__device__ __nv_bfloat16 g_loX[(size_t)3 * NX];
__device__ __nv_bfloat16 g_hiW[(size_t)4 * NW];    // converted Wq,Wk,Wv,Wo
__device__ __nv_bfloat16 g_loW[(size_t)4 * NW];
__device__ __nv_bfloat16 g_hiQKV[(size_t)3 * NX];  // projected Q,K,V hi/lo
__device__ __nv_bfloat16 g_loQKV[(size_t)3 * NX];
__device__ __nv_bfloat16 g_hiC[NX];                // attention context hi/lo
__device__ __nv_bfloat16 g_loC[NX];

// ---------------- helpers ----------------
__device__ __forceinline__ uint32_t smem_u32(const void* p) {
    uint32_t a;
    asm("{ .reg .u64 t; cvta.to.shared.u64 t, %1; cvt.u32.u64 %0, t; }" : "=r"(a) : "l"(p));
    return a;
}
__device__ __forceinline__ void ldsm4(uint32_t* r, uint32_t a) {
    asm volatile("ldmatrix.sync.aligned.m8n8.x4.shared.b16 {%0,%1,%2,%3}, [%4];"
        : "=r"(r[0]), "=r"(r[1]), "=r"(r[2]), "=r"(r[3]) : "r"(a));
}
__device__ __forceinline__ void ldsm4t(uint32_t* r, uint32_t a) {
    asm volatile("ldmatrix.sync.aligned.m8n8.x4.trans.shared.b16 {%0,%1,%2,%3}, [%4];"
        : "=r"(r[0]), "=r"(r[1]), "=r"(r[2]), "=r"(r[3]) : "r"(a));
}
__device__ __forceinline__ void mma_bf16(float* d, const uint32_t* a, const uint32_t* b) {
    asm volatile("mma.sync.aligned.m16n8k16.row.col.f32.bf16.bf16.f32 "
        "{%0,%1,%2,%3},{%4,%5,%6,%7},{%8,%9},{%0,%1,%2,%3};"
        : "+f"(d[0]), "+f"(d[1]), "+f"(d[2]), "+f"(d[3])
        : "r"(a[0]), "r"(a[1]), "r"(a[2]), "r"(a[3]), "r"(b[0]), "r"(b[1]));
}
// 64B-row swizzle (GEMM tiles)
#define SWB(row, ch) (((row) << 6) + ((((ch) ^ (((row) >> 1) & 3))) << 4))
// 128B-row swizzle (attention tiles)
#define SWB128(row, ch) (((row) << 7) + ((((ch) ^ ((row) & 7))) << 4))

__device__ __forceinline__ void split_pair(float a, float b, uint32_t& hi, uint32_t& lo) {
    __nv_bfloat16 ha = __float2bfloat16(a), hb = __float2bfloat16(b);
    __nv_bfloat162 hp(ha, hb);
    __nv_bfloat162 lp(__float2bfloat16(a - __bfloat162float(ha)),
                      __float2bfloat16(b - __bfloat162float(hb)));
    hi = *(uint32_t*)&hp;
    lo = *(uint32_t*)&lp;
}

// ---------------- fp32 -> bf16 hi/lo split conversion ----------------
__global__ void __launch_bounds__(256) conv_split(
    const float* __restrict__ src, __nv_bfloat16* __restrict__ hi,
    __nv_bfloat16* __restrict__ lo)
{
    const size_t i = ((size_t)blockIdx.x * 256 + threadIdx.x) * 4;
    float4 v = *(const float4*)(src + i);
    uint32_t h01, l01, h23, l23;
    split_pair(v.x, v.y, h01, l01);
    split_pair(v.z, v.w, h23, l23);
    *(uint2*)(hi + i) = make_uint2(h01, h23);
    *(uint2*)(lo + i) = make_uint2(l01, l23);
}

// ---------------------------------------------------------------------------
// mma.sync bf16x3 GEMM: C[128 x 128 per block] = A * W^T + bias
// 256 threads = 8 warps (4 m-warps x 2 n-warps), warp tile 32x64.
// Dyn smem: double buffer of 32KB: Ahi 8K | Alo 8K | Whi 8K | Wlo 8K.
// ---------------------------------------------------------------------------
#define GEMM_SMEM 65536

template <bool SPLIT>
__device__ __forceinline__ void gemm_mma_core(
    const __nv_bfloat16* __restrict__ Ahi, const __nv_bfloat16* __restrict__ Alo,
    const __nv_bfloat16* __restrict__ Whi, const __nv_bfloat16* __restrict__ Wlo,
    const float* __restrict__ bias, float* __restrict__ Cf,
    __nv_bfloat16* __restrict__ Chi, __nv_bfloat16* __restrict__ Clo)
{
    extern __shared__ char smbuf[];
    const int tid = threadIdx.x, lane = tid & 31, wid = tid >> 5;
    const int warpM = wid & 3, warpN = wid >> 2;
    const int row0 = blockIdx.y * 128, col0 = blockIdx.x * 128;
    const uint32_t sb = smem_u32(smbuf);

    // global load mapping: per tile 128 rows x 64B; 2 passes of 256 threads
    const int grow = tid >> 2, gch = tid & 3;   // row 0..63 (+j*64), ch 0..3
    const size_t aoff0 = (size_t)(row0 + grow) * (DMODEL * 2) + gch * 16;
    const size_t aoff1 = aoff0 + (size_t)64 * (DMODEL * 2);
    const size_t woff0 = (size_t)(col0 + grow) * (DMODEL * 2) + gch * 16;
    const size_t woff1 = woff0 + (size_t)64 * (DMODEL * 2);
    const uint32_t d0 = SWB(grow, gch);
    const uint32_t d1 = SWB(grow + 64, gch);

    float acc[2][8][4];
#pragma unroll
    for (int mt = 0; mt < 2; mt++)
#pragma unroll
        for (int nt = 0; nt < 8; nt++)
#pragma unroll
            for (int e = 0; e < 4; e++) acc[mt][nt][e] = 0.f;

    uint4 pre[8];
    pre[0] = *(const uint4*)((const char*)Ahi + aoff0);
    pre[1] = *(const uint4*)((const char*)Ahi + aoff1);
    pre[2] = *(const uint4*)((const char*)Alo + aoff0);
    pre[3] = *(const uint4*)((const char*)Alo + aoff1);
    pre[4] = *(const uint4*)((const char*)Whi + woff0);
    pre[5] = *(const uint4*)((const char*)Whi + woff1);
    pre[6] = *(const uint4*)((const char*)Wlo + woff0);
    pre[7] = *(const uint4*)((const char*)Wlo + woff1);

    const int arowl = warpM * 32 + (lane & 7) + ((lane >> 3) & 1) * 8;
    const int achl  = (lane >> 4) & 1;
    const int brow8 = (lane & 7) + ((lane >> 4) & 1) * 8;   // + warpN*64 + np*16
    const int bchl  = (lane >> 3) & 1;

    int buf = 0;
    for (int c = 0; c < 32; c++) {
        char* base = smbuf + buf * 32768;
        *(uint4*)(base + 0     + d0) = pre[0];
        *(uint4*)(base + 0     + d1) = pre[1];
        *(uint4*)(base + 8192  + d0) = pre[2];
        *(uint4*)(base + 8192  + d1) = pre[3];
        *(uint4*)(base + 16384 + d0) = pre[4];
        *(uint4*)(base + 16384 + d1) = pre[5];
        *(uint4*)(base + 24576 + d0) = pre[6];
        *(uint4*)(base + 24576 + d1) = pre[7];
        __syncthreads();

        if (c + 1 < 32) {
            const size_t cb = (size_t)(c + 1) * 64;
            pre[0] = *(const uint4*)((const char*)Ahi + aoff0 + cb);
            pre[1] = *(const uint4*)((const char*)Ahi + aoff1 + cb);
            pre[2] = *(const uint4*)((const char*)Alo + aoff0 + cb);
            pre[3] = *(const uint4*)((const char*)Alo + aoff1 + cb);
            pre[4] = *(const uint4*)((const char*)Whi + woff0 + cb);
            pre[5] = *(const uint4*)((const char*)Whi + woff1 + cb);
            pre[6] = *(const uint4*)((const char*)Wlo + woff0 + cb);
            pre[7] = *(const uint4*)((const char*)Wlo + woff1 + cb);
        }

        const uint32_t bb = sb + buf * 32768;
#pragma unroll
        for (int ks = 0; ks < 2; ks++) {
            uint32_t a_hi[2][4], a_lo[2][4], b_hi[4][4], b_lo[4][4];
#pragma unroll
            for (int mt = 0; mt < 2; mt++) {
                const uint32_t ao = SWB(arowl + mt * 16, ks * 2 + achl);
                ldsm4(a_hi[mt], bb + 0    + ao);
                ldsm4(a_lo[mt], bb + 8192 + ao);
            }
#pragma unroll
            for (int np = 0; np < 4; np++) {
                const uint32_t bo = SWB(warpN * 64 + np * 16 + brow8, ks * 2 + bchl);
                ldsm4(b_hi[np], bb + 16384 + bo);
                ldsm4(b_lo[np], bb + 24576 + bo);
            }
#pragma unroll
            for (int mt = 0; mt < 2; mt++)
#pragma unroll
                for (int nt = 0; nt < 8; nt++) {
                    const uint32_t* bh = &b_hi[nt >> 1][(nt & 1) * 2];
                    const uint32_t* bl = &b_lo[nt >> 1][(nt & 1) * 2];
                    mma_bf16(acc[mt][nt], a_hi[mt], bh);
                    mma_bf16(acc[mt][nt], a_hi[mt], bl);
                    mma_bf16(acc[mt][nt], a_lo[mt], bh);
                }
        }
        buf ^= 1;
    }

#pragma unroll
    for (int mt = 0; mt < 2; mt++) {
        const int r = row0 + warpM * 32 + mt * 16 + (lane >> 2);
#pragma unroll
        for (int nt = 0; nt < 8; nt++) {
            const int col = col0 + warpN * 64 + nt * 8 + (lane & 3) * 2;
            const float b0 = bias[col], b1 = bias[col + 1];
            const float o0 = acc[mt][nt][0] + b0, o1 = acc[mt][nt][1] + b1;
            const float o2 = acc[mt][nt][2] + b0, o3 = acc[mt][nt][3] + b1;
            if (SPLIT) {
                uint32_t h01, l01, h23, l23;
                split_pair(o0, o1, h01, l01);
                split_pair(o2, o3, h23, l23);
                *(uint32_t*)&Chi[(size_t)r * DMODEL + col]       = h01;
                *(uint32_t*)&Clo[(size_t)r * DMODEL + col]       = l01;
                *(uint32_t*)&Chi[(size_t)(r + 8) * DMODEL + col] = h23;
                *(uint32_t*)&Clo[(size_t)(r + 8) * DMODEL + col] = l23;
            } else {
                *(float2*)&Cf[(size_t)r * DMODEL + col]       = make_float2(o0, o1);
                *(float2*)&Cf[(size_t)(r + 8) * DMODEL + col] = make_float2(o2, o3);
            }
        }
    }
}

__global__ void __launch_bounds__(256) qkv_mma(
    const float* __restrict__ bq, const float* __restrict__ bk, const float* __restrict__ bv)
{
    const int z = blockIdx.z;
    const float* bias = (z == 0) ? bq : (z == 1) ? bk : bv;
    gemm_mma_core<true>(g_hiX + z * NX, g_loX + z * NX,
                        g_hiW + z * NW, g_loW + z * NW, bias,
                        nullptr, g_hiQKV + z * NX, g_loQKV + z * NX);
}

__global__ void __launch_bounds__(256) out_mma(
    const float* __restrict__ bo, float* __restrict__ C)
{
    gemm_mma_core<false>(g_hiC, g_loC, g_hiW + 3 * NW, g_loW + 3 * NW, bo,
                         C, nullptr, nullptr);
}

// ---------------------------------------------------------------------------
// Fused flash attention (unchanged from R7, passing).
// ---------------------------------------------------------------------------
#define ATT_SMEM (65536 + 512)

__global__ void __launch_bounds__(256) attn_fused(float* __restrict__ attn)
{
    extern __shared__ char sm[];
    const uint32_t sQh = smem_u32(sm);
    const uint32_t sQl = sQh + 16384;
    const uint32_t sKh = sQh + 32768;
    const uint32_t sKl = sQh + 40960;
    const uint32_t sVh = sQh + 49152;
    const uint32_t sVl = sQh + 57344;
    float* rsum = (float*)(sm + 65536);

    const int tid = threadIdx.x, lane = tid & 31, wid = tid >> 5;
    const int warpM = wid & 3, warpN = wid >> 2;
    const int p = blockIdx.y, bb = p >> 4, h = p & 15;
    const int row0 = blockIdx.x * 128;

#pragma unroll
    for (int ps = 0; ps < 4; ps++) {
        const int u = tid + ps * 256;
        const int row = u >> 3, ch = u & 7;
        const size_t ge = (size_t)(bb * S_LEN + row0 + row) * DMODEL + h * HDIM + ch * 8;
        const uint32_t so = SWB128(row, ch);
        *(uint4*)(sm + so)         = *(const uint4*)(g_hiQKV + ge);
        *(uint4*)(sm + 16384 + so) = *(const uint4*)(g_loQKV + ge);
    }
    if (tid < 128) rsum[tid] = 0.f;

    const int arowl = warpM * 32 + (lane & 7) + ((lane >> 3) & 1) * 8;
    const int achl  = (lane >> 4) & 1;
    const int browl = warpN * 32 + (lane & 7) + ((lane >> 4) & 1) * 8;
    const int bchl  = (lane >> 3) & 1;
    const int vrowl = (lane & 7) + ((lane >> 3) & 1) * 8;
    const int vtog  = (lane >> 4) & 1;
    const float sc = 0.125f;

    // ---------------- pass 1: rowsums (hi-only) ----------------
    float rs[4] = {0.f, 0.f, 0.f, 0.f};
    for (int c = 0; c < 32; c++) {
        const int c0 = c * 64;
        __syncthreads();
#pragma unroll
        for (int ps = 0; ps < 2; ps++) {
            const int u = tid + ps * 256;
            const int row = u >> 3, ch = u & 7;
            const size_t ge = NX + (size_t)(bb * S_LEN + c0 + row) * DMODEL + h * HDIM + ch * 8;
            *(uint4*)(sm + 32768 + SWB128(row, ch)) = *(const uint4*)(g_hiQKV + ge);
        }
        __syncthreads();

        float acc[2][4][4];
#pragma unroll
        for (int mt = 0; mt < 2; mt++)
#pragma unroll
            for (int nt = 0; nt < 4; nt++)
#pragma unroll
                for (int e = 0; e < 4; e++) acc[mt][nt][e] = 0.f;
#pragma unroll
        for (int ks = 0; ks < 4; ks++) {
            uint32_t a_hi[2][4], b_hi[2][4];
#pragma unroll
            for (int mt = 0; mt < 2; mt++)
                ldsm4(a_hi[mt], sQh + SWB128(arowl + mt * 16, ks * 2 + achl));
#pragma unroll
            for (int np = 0; np < 2; np++)
                ldsm4(b_hi[np], sKh + SWB128(browl + np * 16, ks * 2 + bchl));
#pragma unroll
            for (int mt = 0; mt < 2; mt++)
#pragma unroll
                for (int nt = 0; nt < 4; nt++)
                    mma_bf16(acc[mt][nt], a_hi[mt], &b_hi[nt >> 1][(nt & 1) * 2]);
        }
#pragma unroll
        for (int mt = 0; mt < 2; mt++)
#pragma unroll
            for (int nt = 0; nt < 4; nt++) {
                rs[mt * 2 + 0] += __expf(acc[mt][nt][0] * sc) + __expf(acc[mt][nt][1] * sc);
                rs[mt * 2 + 1] += __expf(acc[mt][nt][2] * sc) + __expf(acc[mt][nt][3] * sc);
            }
    }
#pragma unroll
    for (int i = 0; i < 4; i++) {
        rs[i] += __shfl_xor_sync(0xffffffffu, rs[i], 1);
        rs[i] += __shfl_xor_sync(0xffffffffu, rs[i], 2);
    }
    if ((lane & 3) == 0) {
#pragma unroll
        for (int mt = 0; mt < 2; mt++) {
            atomicAdd(&rsum[warpM * 32 + mt * 16 + (lane >> 2)],     rs[mt * 2 + 0]);
            atomicAdd(&rsum[warpM * 32 + mt * 16 + (lane >> 2) + 8], rs[mt * 2 + 1]);
        }
    }
    __syncthreads();
    if (tid < 128) rsum[tid] = 1.0f / rsum[tid];
    __syncthreads();
    float rinv[2][2];
#pragma unroll
    for (int mt = 0; mt < 2; mt++) {
        rinv[mt][0] = rsum[warpM * 32 + mt * 16 + (lane >> 2)];
        rinv[mt][1] = rsum[warpM * 32 + mt * 16 + (lane >> 2) + 8];
    }

    // ---------------- pass 2: attn write + PV ----------------
    float ctx[2][8][4];
#pragma unroll
    for (int mt = 0; mt < 2; mt++)
#pragma unroll
        for (int nt = 0; nt < 8; nt++)
#pragma unroll
            for (int e = 0; e < 4; e++) ctx[mt][nt][e] = 0.f;

    for (int c = 0; c < 32; c++) {
        const int c0 = c * 64;
        __syncthreads();
#pragma unroll
        for (int ps = 0; ps < 2; ps++) {
            const int u = tid + ps * 256;
            const int row = u >> 3, ch = u & 7;
            const uint32_t so = SWB128(row, ch);
            const size_t geK = NX     + (size_t)(bb * S_LEN + c0 + row) * DMODEL + h * HDIM + ch * 8;
            const size_t geV = 2 * NX + (size_t)(bb * S_LEN + c0 + row) * DMODEL + h * HDIM + ch * 8;
            *(uint4*)(sm + 32768 + so) = *(const uint4*)(g_hiQKV + geK);
            *(uint4*)(sm + 40960 + so) = *(const uint4*)(g_loQKV + geK);
            *(uint4*)(sm + 49152 + so) = *(const uint4*)(g_hiQKV + geV);
            *(uint4*)(sm + 57344 + so) = *(const uint4*)(g_loQKV + geV);
        }
        __syncthreads();

        float acc[2][4][4];
#pragma unroll
        for (int mt = 0; mt < 2; mt++)
#pragma unroll
            for (int nt = 0; nt < 4; nt++)
#pragma unroll
                for (int e = 0; e < 4; e++) acc[mt][nt][e] = 0.f;
#pragma unroll
        for (int ks = 0; ks < 4; ks++) {
            uint32_t a_hi[2][4], a_lo[2][4], b_hi[2][4], b_lo[2][4];
#pragma unroll
            for (int mt = 0; mt < 2; mt++) {
                const uint32_t ao = SWB128(arowl + mt * 16, ks * 2 + achl);
                ldsm4(a_hi[mt], sQh + ao);
                ldsm4(a_lo[mt], sQl + ao);
            }
#pragma unroll
            for (int np = 0; np < 2; np++) {
                const uint32_t bo = SWB128(browl + np * 16, ks * 2 + bchl);
                ldsm4(b_hi[np], sKh + bo);
                ldsm4(b_lo[np], sKl + bo);
            }
#pragma unroll
            for (int mt = 0; mt < 2; mt++)
#pragma unroll
                for (int nt = 0; nt < 4; nt++) {
                    const uint32_t* bh = &b_hi[nt >> 1][(nt & 1) * 2];
                    const uint32_t* bl = &b_lo[nt >> 1][(nt & 1) * 2];
                    mma_bf16(acc[mt][nt], a_hi[mt], bh);
                    mma_bf16(acc[mt][nt], a_hi[mt], bl);
                    mma_bf16(acc[mt][nt], a_lo[mt], bh);
                }
        }

#pragma unroll
        for (int mt = 0; mt < 2; mt++) {
            const int r = row0 + warpM * 32 + mt * 16 + (lane >> 2);
#pragma unroll
            for (int nt = 0; nt < 4; nt++) {
                const int col = c0 + warpN * 32 + nt * 8 + (lane & 3) * 2;
                const float p0 = __expf(acc[mt][nt][0] * sc) * rinv[mt][0];
                const float p1 = __expf(acc[mt][nt][1] * sc) * rinv[mt][0];
                const float p2 = __expf(acc[mt][nt][2] * sc) * rinv[mt][1];
                const float p3 = __expf(acc[mt][nt][3] * sc) * rinv[mt][1];
                const size_t gi = ((size_t)(p * S_LEN) + r) * S_LEN + col;
                *(float2*)&attn[gi]             = make_float2(p0, p1);
                *(float2*)&attn[gi + 8 * S_LEN] = make_float2(p2, p3);
                acc[mt][nt][0] = p0; acc[mt][nt][1] = p1;
                acc[mt][nt][2] = p2; acc[mt][nt][3] = p3;
            }
        }

#pragma unroll
        for (int kg = 0; kg < 2; kg++) {
            uint32_t ah[2][4], al[2][4];
#pragma unroll
            for (int mt = 0; mt < 2; mt++) {
                split_pair(acc[mt][2 * kg][0],     acc[mt][2 * kg][1],     ah[mt][0], al[mt][0]);
                split_pair(acc[mt][2 * kg][2],     acc[mt][2 * kg][3],     ah[mt][1], al[mt][1]);
                split_pair(acc[mt][2 * kg + 1][0], acc[mt][2 * kg + 1][1], ah[mt][2], al[mt][2]);
                split_pair(acc[mt][2 * kg + 1][2], acc[mt][2 * kg + 1][3], ah[mt][3], al[mt][3]);
            }
            uint32_t bh[4][4], bl[4][4];
            const int kb = warpN * 32 + kg * 16;
#pragma unroll
            for (int ld = 0; ld < 4; ld++) {
                const uint32_t bo = SWB128(kb + vrowl, ld * 2 + vtog);
                ldsm4t(bh[ld], sVh + bo);
                ldsm4t(bl[ld], sVl + bo);
            }
#pragma unroll
            for (int mt = 0; mt < 2; mt++)
#pragma unroll
                for (int nt = 0; nt < 8; nt++) {
                    const uint32_t* bhp = &bh[nt >> 1][(nt & 1) * 2];
                    const uint32_t* blp = &bl[nt >> 1][(nt & 1) * 2];
                    mma_bf16(ctx[mt][nt], ah[mt], bhp);
                    mma_bf16(ctx[mt][nt], ah[mt], blp);
                    mma_bf16(ctx[mt][nt], al[mt], bhp);
                }
        }
    }

    __syncthreads();
    float* red = (float*)sm;
    if (warpN == 1) {
#pragma unroll
        for (int mt = 0; mt < 2; mt++) {
            const int rl = warpM * 32 + mt * 16 + (lane >> 2);
#pragma unroll
            for (int nt = 0; nt < 8; nt++) {
                const int col = nt * 8 + (lane & 3) * 2;
                *(float2*)&red[rl * 64 + col]       = make_float2(ctx[mt][nt][0], ctx[mt][nt][1]);
                *(float2*)&red[(rl + 8) * 64 + col] = make_float2(ctx[mt][nt][2], ctx[mt][nt][3]);
            }
        }
    }
    __syncthreads();
    if (warpN == 0) {
#pragma unroll
        for (int mt = 0; mt < 2; mt++) {
            const int rl = warpM * 32 + mt * 16 + (lane >> 2);
            const size_t gr0 = (size_t)(bb * S_LEN + row0 + rl) * DMODEL + h * HDIM;
            const size_t gr1 = gr0 + (size_t)8 * DMODEL;
#pragma unroll
            for (int nt = 0; nt < 8; nt++) {
                const int col = nt * 8 + (lane & 3) * 2;
                float2 s0 = *(float2*)&red[rl * 64 + col];
                float2 s1 = *(float2*)&red[(rl + 8) * 64 + col];
                const float o0 = ctx[mt][nt][0] + s0.x, o1 = ctx[mt][nt][1] + s0.y;
                const float o2 = ctx[mt][nt][2] + s1.x, o3 = ctx[mt][nt][3] + s1.y;
                uint32_t h01, l01, h23, l23;
                split_pair(o0, o1, h01, l01);
                split_pair(o2, o3, h23, l23);
                *(uint32_t*)&g_hiC[gr0 + col] = h01;
                *(uint32_t*)&g_loC[gr0 + col] = l01;
                *(uint32_t*)&g_hiC[gr1 + col] = h23;
                *(uint32_t*)&g_loC[gr1 + col] = l23;
            }
        }
    }
}

// ---------------------------------------------------------------------------
extern "C" void kernel_launch(void* const* d_in, const int* in_sizes, int n_in,
                              void* d_out, int out_size) {
    const float* query = (const float*)d_in[0];
    const float* key_  = (const float*)d_in[1];
    const float* value = (const float*)d_in[2];
    const float* Wq = (const float*)d_in[3];
    const float* bq = (const float*)d_in[4];
    const float* Wk = (const float*)d_in[5];
    const float* bk = (const float*)d_in[6];
    const float* Wv = (const float*)d_in[7];
    const float* bv = (const float*)d_in[8];
    const float* Wo = (const float*)d_in[9];
    const float* bo = (const float*)d_in[10];

    float* outp = (float*)d_out;
    float* attn = outp + NX;          // tuple output: (out, attn)

    static int attr_set = 0;
    if (!attr_set) {
        cudaFuncSetAttribute(attn_fused, cudaFuncAttributeMaxDynamicSharedMemorySize, ATT_SMEM);
        cudaFuncSetAttribute(qkv_mma, cudaFuncAttributeMaxDynamicSharedMemorySize, GEMM_SMEM);
        cudaFuncSetAttribute(out_mma, cudaFuncAttributeMaxDynamicSharedMemorySize, GEMM_SMEM);
        attr_set = 1;
    }

    __nv_bfloat16 *hiX, *loX, *hiW, *loW;
    cudaGetSymbolAddress((void**)&hiX, g_hiX);
    cudaGetSymbolAddress((void**)&loX, g_loX);
    cudaGetSymbolAddress((void**)&hiW, g_hiW);
    cudaGetSymbolAddress((void**)&loW, g_loW);

    conv_split<<<NX / 1024, 256>>>(query, hiX, loX);
    conv_split<<<NX / 1024, 256>>>(key_,  hiX + NX, loX + NX);
    conv_split<<<NX / 1024, 256>>>(value, hiX + 2 * NX, loX + 2 * NX);
    conv_split<<<NW / 1024, 256>>>(Wq, hiW, loW);
    conv_split<<<NW / 1024, 256>>>(Wk, hiW + NW, loW + NW);
    conv_split<<<NW / 1024, 256>>>(Wv, hiW + 2 * NW, loW + 2 * NW);
    conv_split<<<NW / 1024, 256>>>(Wo, hiW + 3 * NW, loW + 3 * NW);

    qkv_mma<<<dim3(DMODEL / 128, MROWS / 128, 3), 256, GEMM_SMEM>>>(bq, bk, bv);
    attn_fused<<<dim3(S_LEN / 128, NPAIRS), 256, ATT_SMEM>>>(attn);
    out_mma<<<dim3(DMODEL / 128, MROWS / 128), 256, GEMM_SMEM>>>(bo, outp);
}

// round 9
// speedup vs baseline: 1.1446x; 1.1446x over previous
#include <cuda_runtime.h>
#include <cuda_fp16.h>
#include <cstdint>

#define S_LEN  2048
#define DMODEL 1024
#define NHEAD  16
#define HDIM   64
#define MROWS  4096   // S*B
#define NPAIRS 32     // B*NHEAD
#define NX     ((size_t)MROWS * DMODEL)
#define NW     ((size_t)DMODEL * DMODEL)

// ---------------- scratch globals (allocation-free rule) ----------------
__device__ __half g_hiX[(size_t)3 * NX];    // converted q/k/v inputs (fp16 hi/lo)
__device__ __half g_loX[(size_t)3 * NX];
__device__ __half g_hiW[(size_t)4 * NW];    // converted Wq,Wk,Wv,Wo
__device__ __half g_loW[(size_t)4 * NW];
__device__ __half g_hiQKV[(size_t)3 * NX];  // projected Q,K,V
__device__ __half g_loQKV[(size_t)3 * NX];  // lo only consumed for Q
__device__ __half g_hiC[NX];                // attention context hi/lo
__device__ __half g_loC[NX];

// ---------------- helpers ----------------
__device__ __forceinline__ uint32_t smem_u32(const void* p) {
    uint32_t a;
    asm("{ .reg .u64 t; cvta.to.shared.u64 t, %1; cvt.u32.u64 %0, t; }" : "=r"(a) : "l"(p));
    return a;
}
__device__ __forceinline__ void ldsm4(uint32_t* r, uint32_t a) {
    asm volatile("ldmatrix.sync.aligned.m8n8.x4.shared.b16 {%0,%1,%2,%3}, [%4];"
        : "=r"(r[0]), "=r"(r[1]), "=r"(r[2]), "=r"(r[3]) : "r"(a));
}
__device__ __forceinline__ void ldsm4t(uint32_t* r, uint32_t a) {
    asm volatile("ldmatrix.sync.aligned.m8n8.x4.trans.shared.b16 {%0,%1,%2,%3}, [%4];"
        : "=r"(r[0]), "=r"(r[1]), "=r"(r[2]), "=r"(r[3]) : "r"(a));
}
__device__ __forceinline__ void mma_f16(float* d, const uint32_t* a, const uint32_t* b) {
    asm volatile("mma.sync.aligned.m16n8k16.row.col.f32.f16.f16.f32 "
        "{%0,%1,%2,%3},{%4,%5,%6,%7},{%8,%9},{%0,%1,%2,%3};"
        : "+f"(d[0]), "+f"(d[1]), "+f"(d[2]), "+f"(d[3])
        : "r"(a[0]), "r"(a[1]), "r"(a[2]), "r"(a[3]), "r"(b[0]), "r"(b[1]));
}
// 64B-row swizzle (GEMM tiles)
#define SWB(row, ch) (((row) << 6) + ((((ch) ^ (((row) >> 1) & 3))) << 4))
// 128B-row swizzle (attention tiles)
#define SWB128(row, ch) (((row) << 7) + ((((ch) ^ ((row) & 7))) << 4))

__device__ __forceinline__ void split_pair(float a, float b, uint32_t& hi, uint32_t& lo) {
    __half ha = __float2half(a), hb = __float2half(b);
    __half2 hp(ha, hb);
    __half2 lp(__float2half(a - __half2float(ha)),
               __float2half(b - __half2float(hb)));
    hi = *(uint32_t*)&hp;
    lo = *(uint32_t*)&lp;
}

// ---------------- fp32 -> fp16 hi/lo split conversion ----------------
__global__ void __launch_bounds__(256) conv_split(
    const float* __restrict__ src, __half* __restrict__ hi,
    __half* __restrict__ lo)
{
    const size_t i = ((size_t)blockIdx.x * 256 + threadIdx.x) * 4;
    float4 v = *(const float4*)(src + i);
    uint32_t h01, l01, h23, l23;
    split_pair(v.x, v.y, h01, l01);
    split_pair(v.z, v.w, h23, l23);
    *(uint2*)(hi + i) = make_uint2(h01, h23);
    *(uint2*)(lo + i) = make_uint2(l01, l23);
}

// ---------------------------------------------------------------------------
// mma.sync fp16x3 GEMM: C[128 x 64 per block] = A * W^T + bias
// 256 threads = 8 warps (4 m-warps x 2 n-warps), warp tile 32x32.
// ---------------------------------------------------------------------------
template <bool SPLIT>
__device__ __forceinline__ void gemm_mma_core(
    const __half* __restrict__ Ahi, const __half* __restrict__ Alo,
    const __half* __restrict__ Whi, const __half* __restrict__ Wlo,
    const float* __restrict__ bias, float* __restrict__ Cf,
    __half* __restrict__ Chi, __half* __restrict__ Clo, bool write_lo)
{
    __shared__ char smbuf[49152];   // 2 x 24576
    const int tid = threadIdx.x, lane = tid & 31, wid = tid >> 5;
    const int warpM = wid & 3, warpN = wid >> 2;
    const int row0 = blockIdx.y * 128, col0 = blockIdx.x * 64;
    const uint32_t sb = smem_u32(smbuf);

    const int grow = tid >> 2, gch = tid & 3;
    const size_t aoff0 = (size_t)(row0 + grow) * (DMODEL * 2) + gch * 16;
    const size_t aoff1 = aoff0 + (size_t)64 * (DMODEL * 2);
    const size_t woff  = (size_t)(col0 + grow) * (DMODEL * 2) + gch * 16;
    const uint32_t dA0 = SWB(grow, gch);
    const uint32_t dA1 = SWB(grow + 64, gch);
    const uint32_t dW  = SWB(grow, gch);

    float acc[2][4][4];
#pragma unroll
    for (int mt = 0; mt < 2; mt++)
#pragma unroll
        for (int nt = 0; nt < 4; nt++)
#pragma unroll
            for (int e = 0; e < 4; e++) acc[mt][nt][e] = 0.f;

    uint4 pre[6];
    pre[0] = *(const uint4*)((const char*)Ahi + aoff0);
    pre[1] = *(const uint4*)((const char*)Ahi + aoff1);
    pre[2] = *(const uint4*)((const char*)Alo + aoff0);
    pre[3] = *(const uint4*)((const char*)Alo + aoff1);
    pre[4] = *(const uint4*)((const char*)Whi + woff);
    pre[5] = *(const uint4*)((const char*)Wlo + woff);

    const int arowl = warpM * 32 + (lane & 7) + ((lane >> 3) & 1) * 8;
    const int achl  = (lane >> 4) & 1;
    const int browl = warpN * 32 + (lane & 7) + ((lane >> 4) & 1) * 8;
    const int bchl  = (lane >> 3) & 1;

    int buf = 0;
    for (int c = 0; c < 32; c++) {
        char* base = smbuf + buf * 24576;
        *(uint4*)(base + 0     + dA0) = pre[0];
        *(uint4*)(base + 0     + dA1) = pre[1];
        *(uint4*)(base + 8192  + dA0) = pre[2];
        *(uint4*)(base + 8192  + dA1) = pre[3];
        *(uint4*)(base + 16384 + dW)  = pre[4];
        *(uint4*)(base + 20480 + dW)  = pre[5];
        __syncthreads();

        if (c + 1 < 32) {
            const size_t cb = (size_t)(c + 1) * 64;
            pre[0] = *(const uint4*)((const char*)Ahi + aoff0 + cb);
            pre[1] = *(const uint4*)((const char*)Ahi + aoff1 + cb);
            pre[2] = *(const uint4*)((const char*)Alo + aoff0 + cb);
            pre[3] = *(const uint4*)((const char*)Alo + aoff1 + cb);
            pre[4] = *(const uint4*)((const char*)Whi + woff + cb);
            pre[5] = *(const uint4*)((const char*)Wlo + woff + cb);
        }

        const uint32_t bb = sb + buf * 24576;
#pragma unroll
        for (int ks = 0; ks < 2; ks++) {
            uint32_t a_hi[2][4], a_lo[2][4], b_hi[2][4], b_lo[2][4];
#pragma unroll
            for (int mt = 0; mt < 2; mt++) {
                const uint32_t ao = SWB(arowl + mt * 16, ks * 2 + achl);
                ldsm4(a_hi[mt], bb + 0    + ao);
                ldsm4(a_lo[mt], bb + 8192 + ao);
            }
#pragma unroll
            for (int np = 0; np < 2; np++) {
                const uint32_t bo = SWB(browl + np * 16, ks * 2 + bchl);
                ldsm4(b_hi[np], bb + 16384 + bo);
                ldsm4(b_lo[np], bb + 20480 + bo);
            }
#pragma unroll
            for (int mt = 0; mt < 2; mt++)
#pragma unroll
                for (int nt = 0; nt < 4; nt++) {
                    const uint32_t* bh = &b_hi[nt >> 1][(nt & 1) * 2];
                    const uint32_t* bl = &b_lo[nt >> 1][(nt & 1) * 2];
                    mma_f16(acc[mt][nt], a_hi[mt], bh);
                    mma_f16(acc[mt][nt], a_hi[mt], bl);
                    mma_f16(acc[mt][nt], a_lo[mt], bh);
                }
        }
        buf ^= 1;
    }

#pragma unroll
    for (int mt = 0; mt < 2; mt++) {
        const int r = row0 + warpM * 32 + mt * 16 + (lane >> 2);
#pragma unroll
        for (int nt = 0; nt < 4; nt++) {
            const int col = col0 + warpN * 32 + nt * 8 + (lane & 3) * 2;
            const float b0 = bias[col], b1 = bias[col + 1];
            const float o0 = acc[mt][nt][0] + b0, o1 = acc[mt][nt][1] + b1;
            const float o2 = acc[mt][nt][2] + b0, o3 = acc[mt][nt][3] + b1;
            if (SPLIT) {
                uint32_t h01, l01, h23, l23;
                split_pair(o0, o1, h01, l01);
                split_pair(o2, o3, h23, l23);
                *(uint32_t*)&Chi[(size_t)r * DMODEL + col]       = h01;
                *(uint32_t*)&Chi[(size_t)(r + 8) * DMODEL + col] = h23;
                if (write_lo) {
                    *(uint32_t*)&Clo[(size_t)r * DMODEL + col]       = l01;
                    *(uint32_t*)&Clo[(size_t)(r + 8) * DMODEL + col] = l23;
                }
            } else {
                *(float2*)&Cf[(size_t)r * DMODEL + col]       = make_float2(o0, o1);
                *(float2*)&Cf[(size_t)(r + 8) * DMODEL + col] = make_float2(o2, o3);
            }
        }
    }
}

__global__ void __launch_bounds__(256, 2) qkv_mma(
    const float* __restrict__ bq, const float* __restrict__ bk, const float* __restrict__ bv)
{
    const int z = blockIdx.z;
    const float* bias = (z == 0) ? bq : (z == 1) ? bk : bv;
    gemm_mma_core<true>(g_hiX + z * NX, g_loX + z * NX,
                        g_hiW + z * NW, g_loW + z * NW, bias,
                        nullptr, g_hiQKV + z * NX, g_loQKV + z * NX,
                        /*write_lo=*/z == 0);   // lo consumed only for Q
}

__global__ void __launch_bounds__(256, 2) out_mma(
    const float* __restrict__ bo, float* __restrict__ C)
{
    gemm_mma_core<false>(g_hiC, g_loC, g_hiW + 3 * NW, g_loW + 3 * NW, bo,
                         C, nullptr, nullptr, false);
}

// ---------------------------------------------------------------------------
// Fused flash attention, fp16. Pass 1: hi-only QK^T -> rowsums.
// Pass 2: 2-term QK (Q hi+lo, K hi) -> exp*rinv -> write attn -> 2-term PV
// (P hi+lo, V hi) -> ctx.
// Smem: Qhi 16K | Qlo 16K | Khi 8K | Vhi 8K | rsum 512
// ---------------------------------------------------------------------------
#define ATT_SMEM (49152 + 512)

__global__ void __launch_bounds__(256) attn_fused(float* __restrict__ attn)
{
    extern __shared__ char sm[];
    const uint32_t sQh = smem_u32(sm);
    const uint32_t sQl = sQh + 16384;
    const uint32_t sKh = sQh + 32768;
    const uint32_t sVh = sQh + 40960;
    float* rsum = (float*)(sm + 49152);

    const int tid = threadIdx.x, lane = tid & 31, wid = tid >> 5;
    const int warpM = wid & 3, warpN = wid >> 2;
    const int p = blockIdx.y, bb = p >> 4, h = p & 15;
    const int row0 = blockIdx.x * 128;

#pragma unroll
    for (int ps = 0; ps < 4; ps++) {
        const int u = tid + ps * 256;
        const int row = u >> 3, ch = u & 7;
        const size_t ge = (size_t)(bb * S_LEN + row0 + row) * DMODEL + h * HDIM + ch * 8;
        const uint32_t so = SWB128(row, ch);
        *(uint4*)(sm + so)         = *(const uint4*)(g_hiQKV + ge);
        *(uint4*)(sm + 16384 + so) = *(const uint4*)(g_loQKV + ge);
    }
    if (tid < 128) rsum[tid] = 0.f;

    const int arowl = warpM * 32 + (lane & 7) + ((lane >> 3) & 1) * 8;
    const int achl  = (lane >> 4) & 1;
    const int browl = warpN * 32 + (lane & 7) + ((lane >> 4) & 1) * 8;
    const int bchl  = (lane >> 3) & 1;
    const int vrowl = (lane & 7) + ((lane >> 3) & 1) * 8;
    const int vtog  = (lane >> 4) & 1;
    const float sc = 0.125f;

    // ---------------- pass 1: rowsums (hi-only) ----------------
    float rs[4] = {0.f, 0.f, 0.f, 0.f};
    for (int c = 0; c < 32; c++) {
        const int c0 = c * 64;
        __syncthreads();
#pragma unroll
        for (int ps = 0; ps < 2; ps++) {
            const int u = tid + ps * 256;
            const int row = u >> 3, ch = u & 7;
            const size_t ge = NX + (size_t)(bb * S_LEN + c0 + row) * DMODEL + h * HDIM + ch * 8;
            *(uint4*)(sm + 32768 + SWB128(row, ch)) = *(const uint4*)(g_hiQKV + ge);
        }
        __syncthreads();

        float acc[2][4][4];
#pragma unroll
        for (int mt = 0; mt < 2; mt++)
#pragma unroll
            for (int nt = 0; nt < 4; nt++)
#pragma unroll
                for (int e = 0; e < 4; e++) acc[mt][nt][e] = 0.f;
#pragma unroll
        for (int ks = 0; ks < 4; ks++) {
            uint32_t a_hi[2][4], b_hi[2][4];
#pragma unroll
            for (int mt = 0; mt < 2; mt++)
                ldsm4(a_hi[mt], sQh + SWB128(arowl + mt * 16, ks * 2 + achl));
#pragma unroll
            for (int np = 0; np < 2; np++)
                ldsm4(b_hi[np], sKh + SWB128(browl + np * 16, ks * 2 + bchl));
#pragma unroll
            for (int mt = 0; mt < 2; mt++)
#pragma unroll
                for (int nt = 0; nt < 4; nt++)
                    mma_f16(acc[mt][nt], a_hi[mt], &b_hi[nt >> 1][(nt & 1) * 2]);
        }
#pragma unroll
        for (int mt = 0; mt < 2; mt++)
#pragma unroll
            for (int nt = 0; nt < 4; nt++) {
                rs[mt * 2 + 0] += __expf(acc[mt][nt][0] * sc) + __expf(acc[mt][nt][1] * sc);
                rs[mt * 2 + 1] += __expf(acc[mt][nt][2] * sc) + __expf(acc[mt][nt][3] * sc);
            }
    }
#pragma unroll
    for (int i = 0; i < 4; i++) {
        rs[i] += __shfl_xor_sync(0xffffffffu, rs[i], 1);
        rs[i] += __shfl_xor_sync(0xffffffffu, rs[i], 2);
    }
    if ((lane & 3) == 0) {
#pragma unroll
        for (int mt = 0; mt < 2; mt++) {
            atomicAdd(&rsum[warpM * 32 + mt * 16 + (lane >> 2)],     rs[mt * 2 + 0]);
            atomicAdd(&rsum[warpM * 32 + mt * 16 + (lane >> 2) + 8], rs[mt * 2 + 1]);
        }
    }
    __syncthreads();
    if (tid < 128) rsum[tid] = 1.0f / rsum[tid];
    __syncthreads();
    float rinv[2][2];
#pragma unroll
    for (int mt = 0; mt < 2; mt++) {
        rinv[mt][0] = rsum[warpM * 32 + mt * 16 + (lane >> 2)];
        rinv[mt][1] = rsum[warpM * 32 + mt * 16 + (lane >> 2) + 8];
    }

    // ---------------- pass 2: attn write + PV ----------------
    float ctx[2][8][4];
#pragma unroll
    for (int mt = 0; mt < 2; mt++)
#pragma unroll
        for (int nt = 0; nt < 8; nt++)
#pragma unroll
            for (int e = 0; e < 4; e++) ctx[mt][nt][e] = 0.f;

    for (int c = 0; c < 32; c++) {
        const int c0 = c * 64;
        __syncthreads();
#pragma unroll
        for (int ps = 0; ps < 2; ps++) {
            const int u = tid + ps * 256;
            const int row = u >> 3, ch = u & 7;
            const uint32_t so = SWB128(row, ch);
            const size_t geK = NX     + (size_t)(bb * S_LEN + c0 + row) * DMODEL + h * HDIM + ch * 8;
            const size_t geV = 2 * NX + (size_t)(bb * S_LEN + c0 + row) * DMODEL + h * HDIM + ch * 8;
            *(uint4*)(sm + 32768 + so) = *(const uint4*)(g_hiQKV + geK);
            *(uint4*)(sm + 40960 + so) = *(const uint4*)(g_hiQKV + geV);
        }
        __syncthreads();

        float acc[2][4][4];
#pragma unroll
        for (int mt = 0; mt < 2; mt++)
#pragma unroll
            for (int nt = 0; nt < 4; nt++)
#pragma unroll
                for (int e = 0; e < 4; e++) acc[mt][nt][e] = 0.f;
#pragma unroll
        for (int ks = 0; ks < 4; ks++) {
            uint32_t a_hi[2][4], a_lo[2][4], b_hi[2][4];
#pragma unroll
            for (int mt = 0; mt < 2; mt++) {
                const uint32_t ao = SWB128(arowl + mt * 16, ks * 2 + achl);
                ldsm4(a_hi[mt], sQh + ao);
                ldsm4(a_lo[mt], sQl + ao);
            }
#pragma unroll
            for (int np = 0; np < 2; np++)
                ldsm4(b_hi[np], sKh + SWB128(browl + np * 16, ks * 2 + bchl));
#pragma unroll
            for (int mt = 0; mt < 2; mt++)
#pragma unroll
                for (int nt = 0; nt < 4; nt++) {
                    const uint32_t* bh = &b_hi[nt >> 1][(nt & 1) * 2];
                    mma_f16(acc[mt][nt], a_hi[mt], bh);
                    mma_f16(acc[mt][nt], a_lo[mt], bh);
                }
        }

#pragma unroll
        for (int mt = 0; mt < 2; mt++) {
            const int r = row0 + warpM * 32 + mt * 16 + (lane >> 2);
#pragma unroll
            for (int nt = 0; nt < 4; nt++) {
                const int col = c0 + warpN * 32 + nt * 8 + (lane & 3) * 2;
                const float p0 = __expf(acc[mt][nt][0] * sc) * rinv[mt][0];
                const float p1 = __expf(acc[mt][nt][1] * sc) * rinv[mt][0];
                const float p2 = __expf(acc[mt][nt][2] * sc) * rinv[mt][1];
                const float p3 = __expf(acc[mt][nt][3] * sc) * rinv[mt][1];
                const size_t gi = ((size_t)(p * S_LEN) + r) * S_LEN + col;
                *(float2*)&attn[gi]             = make_float2(p0, p1);
                *(float2*)&attn[gi + 8 * S_LEN] = make_float2(p2, p3);
                acc[mt][nt][0] = p0; acc[mt][nt][1] = p1;
                acc[mt][nt][2] = p2; acc[mt][nt][3] = p3;
            }
        }

        // PV: this warp handles its 32 keys (2 groups of 16), full hd=64
#pragma unroll
        for (int kg = 0; kg < 2; kg++) {
            uint32_t ah[2][4], al[2][4];
#pragma unroll
            for (int mt = 0; mt < 2; mt++) {
                split_pair(acc[mt][2 * kg][0],     acc[mt][2 * kg][1],     ah[mt][0], al[mt][0]);
                split_pair(acc[mt][2 * kg][2],     acc[mt][2 * kg][3],     ah[mt][1], al[mt][1]);
                split_pair(acc[mt][2 * kg + 1][0], acc[mt][2 * kg + 1][1], ah[mt][2], al[mt][2]);
                split_pair(acc[mt][2 * kg + 1][2], acc[mt][2 * kg + 1][3], ah[mt][3], al[mt][3]);
            }
            uint32_t bh[4][4];
            const int kb = warpN * 32 + kg * 16;
#pragma unroll
            for (int ld = 0; ld < 4; ld++)
                ldsm4t(bh[ld], sVh + SWB128(kb + vrowl, ld * 2 + vtog));
#pragma unroll
            for (int mt = 0; mt < 2; mt++)
#pragma unroll
                for (int nt = 0; nt < 8; nt++) {
                    const uint32_t* bhp = &bh[nt >> 1][(nt & 1) * 2];
                    mma_f16(ctx[mt][nt], ah[mt], bhp);
                    mma_f16(ctx[mt][nt], al[mt], bhp);
                }
        }
    }

    // cross-warpN ctx reduction via smem (reuse Q region: 128x64 fp32 = 32KB)
    __syncthreads();
    float* red = (float*)sm;
    if (warpN == 1) {
#pragma unroll
        for (int mt = 0; mt < 2; mt++) {
            const int rl = warpM * 32 + mt * 16 + (lane >> 2);
#pragma unroll
            for (int nt = 0; nt < 8; nt++) {
                const int col = nt * 8 + (lane & 3) * 2;
                *(float2*)&red[rl * 64 + col]       = make_float2(ctx[mt][nt][0], ctx[mt][nt][1]);
                *(float2*)&red[(rl + 8) * 64 + col] = make_float2(ctx[mt][nt][2], ctx[mt][nt][3]);
            }
        }
    }
    __syncthreads();
    if (warpN == 0) {
#pragma unroll
        for (int mt = 0; mt < 2; mt++) {
            const int rl = warpM * 32 + mt * 16 + (lane >> 2);
            const size_t gr0 = (size_t)(bb * S_LEN + row0 + rl) * DMODEL + h * HDIM;
            const size_t gr1 = gr0 + (size_t)8 * DMODEL;
#pragma unroll
            for (int nt = 0; nt < 8; nt++) {
                const int col = nt * 8 + (lane & 3) * 2;
                float2 s0 = *(float2*)&red[rl * 64 + col];
                float2 s1 = *(float2*)&red[(rl + 8) * 64 + col];
                const float o0 = ctx[mt][nt][0] + s0.x, o1 = ctx[mt][nt][1] + s0.y;
                const float o2 = ctx[mt][nt][2] + s1.x, o3 = ctx[mt][nt][3] + s1.y;
                uint32_t h01, l01, h23, l23;
                split_pair(o0, o1, h01, l01);
                split_pair(o2, o3, h23, l23);
                *(uint32_t*)&g_hiC[gr0 + col] = h01;
                *(uint32_t*)&g_loC[gr0 + col] = l01;
                *(uint32_t*)&g_hiC[gr1 + col] = h23;
                *(uint32_t*)&g_loC[gr1 + col] = l23;
            }
        }
    }
}

// ---------------------------------------------------------------------------
extern "C" void kernel_launch(void* const* d_in, const int* in_sizes, int n_in,
                              void* d_out, int out_size) {
    const float* query = (const float*)d_in[0];
    const float* key_  = (const float*)d_in[1];
    const float* value = (const float*)d_in[2];
    const float* Wq = (const float*)d_in[3];
    const float* bq = (const float*)d_in[4];
    const float* Wk = (const float*)d_in[5];
    const float* bk = (const float*)d_in[6];
    const float* Wv = (const float*)d_in[7];
    const float* bv = (const float*)d_in[8];
    const float* Wo = (const float*)d_in[9];
    const float* bo = (const float*)d_in[10];

    float* outp = (float*)d_out;
    float* attn = outp + NX;          // tuple output: (out, attn)

    static int attr_set = 0;
    if (!attr_set) {
        cudaFuncSetAttribute(attn_fused, cudaFuncAttributeMaxDynamicSharedMemorySize, ATT_SMEM);
        attr_set = 1;
    }

    __half *hiX, *loX, *hiW, *loW;
    cudaGetSymbolAddress((void**)&hiX, g_hiX);
    cudaGetSymbolAddress((void**)&loX, g_loX);
    cudaGetSymbolAddress((void**)&hiW, g_hiW);
    cudaGetSymbolAddress((void**)&loW, g_loW);

    conv_split<<<NX / 1024, 256>>>(query, hiX, loX);
    conv_split<<<NX / 1024, 256>>>(key_,  hiX + NX, loX + NX);
    conv_split<<<NX / 1024, 256>>>(value, hiX + 2 * NX, loX + 2 * NX);
    conv_split<<<NW / 1024, 256>>>(Wq, hiW, loW);
    conv_split<<<NW / 1024, 256>>>(Wk, hiW + NW, loW + NW);
    conv_split<<<NW / 1024, 256>>>(Wv, hiW + 2 * NW, loW + 2 * NW);
    conv_split<<<NW / 1024, 256>>>(Wo, hiW + 3 * NW, loW + 3 * NW);

    qkv_mma<<<dim3(DMODEL / 64, MROWS / 128, 3), 256>>>(bq, bk, bv);
    attn_fused<<<dim3(S_LEN / 128, NPAIRS), 256, ATT_SMEM>>>(attn);
    out_mma<<<dim3(DMODEL / 64, MROWS / 128), 256>>>(bo, outp);
}

// round 10
// speedup vs baseline: 1.2869x; 1.1244x over previous
#include <cuda_runtime.h>
#include <cuda_fp16.h>
#include <cstdint>

#define S_LEN  2048
#define DMODEL 1024
#define NHEAD  16
#define HDIM   64
#define MROWS  4096   // S*B
#define NPAIRS 32     // B*NHEAD
#define NX     ((size_t)MROWS * DMODEL)
#define NW     ((size_t)DMODEL * DMODEL)

// ---------------- scratch globals (allocation-free rule) ----------------
__device__ __half g_hiX[(size_t)3 * NX];    // converted q/k/v inputs (fp16 hi/lo)
__device__ __half g_loX[(size_t)3 * NX];
__device__ __half g_hiW[(size_t)4 * NW];    // converted Wq,Wk,Wv,Wo (hi only)
__device__ __half g_hiQKV[(size_t)3 * NX];  // projected Q,K,V (hi only)
__device__ __half g_hiC[NX];                // attention context hi/lo
__device__ __half g_loC[NX];

// ---------------- helpers ----------------
__device__ __forceinline__ uint32_t smem_u32(const void* p) {
    uint32_t a;
    asm("{ .reg .u64 t; cvta.to.shared.u64 t, %1; cvt.u32.u64 %0, t; }" : "=r"(a) : "l"(p));
    return a;
}
__device__ __forceinline__ void ldsm4(uint32_t* r, uint32_t a) {
    asm volatile("ldmatrix.sync.aligned.m8n8.x4.shared.b16 {%0,%1,%2,%3}, [%4];"
        : "=r"(r[0]), "=r"(r[1]), "=r"(r[2]), "=r"(r[3]) : "r"(a));
}
__device__ __forceinline__ void ldsm4t(uint32_t* r, uint32_t a) {
    asm volatile("ldmatrix.sync.aligned.m8n8.x4.trans.shared.b16 {%0,%1,%2,%3}, [%4];"
        : "=r"(r[0]), "=r"(r[1]), "=r"(r[2]), "=r"(r[3]) : "r"(a));
}
__device__ __forceinline__ void mma_f16(float* d, const uint32_t* a, const uint32_t* b) {
    asm volatile("mma.sync.aligned.m16n8k16.row.col.f32.f16.f16.f32 "
        "{%0,%1,%2,%3},{%4,%5,%6,%7},{%8,%9},{%0,%1,%2,%3};"
        : "+f"(d[0]), "+f"(d[1]), "+f"(d[2]), "+f"(d[3])
        : "r"(a[0]), "r"(a[1]), "r"(a[2]), "r"(a[3]), "r"(b[0]), "r"(b[1]));
}
// 64B-row swizzle (GEMM tiles)
#define SWB(row, ch) (((row) << 6) + ((((ch) ^ (((row) >> 1) & 3))) << 4))
// 128B-row swizzle (attention tiles)
#define SWB128(row, ch) (((row) << 7) + ((((ch) ^ ((row) & 7))) << 4))

__device__ __forceinline__ void split_pair(float a, float b, uint32_t& hi, uint32_t& lo) {
    __half ha = __float2half(a), hb = __float2half(b);
    __half2 hp(ha, hb);
    __half2 lp(__float2half(a - __half2float(ha)),
               __float2half(b - __half2float(hb)));
    hi = *(uint32_t*)&hp;
    lo = *(uint32_t*)&lp;
}
__device__ __forceinline__ uint32_t pack_h2(float a, float b) {
    __half2 h = __floats2half2_rn(a, b);
    return *(uint32_t*)&h;
}

// ---------------- fp32 -> fp16 conversions ----------------
__global__ void __launch_bounds__(256) conv_split(
    const float* __restrict__ src, __half* __restrict__ hi,
    __half* __restrict__ lo)
{
    const size_t i = ((size_t)blockIdx.x * 256 + threadIdx.x) * 4;
    float4 v = *(const float4*)(src + i);
    uint32_t h01, l01, h23, l23;
    split_pair(v.x, v.y, h01, l01);
    split_pair(v.z, v.w, h23, l23);
    *(uint2*)(hi + i) = make_uint2(h01, h23);
    *(uint2*)(lo + i) = make_uint2(l01, l23);
}
__global__ void __launch_bounds__(256) conv_hi(
    const float* __restrict__ src, __half* __restrict__ hi)
{
    const size_t i = ((size_t)blockIdx.x * 256 + threadIdx.x) * 4;
    float4 v = *(const float4*)(src + i);
    *(uint2*)(hi + i) = make_uint2(pack_h2(v.x, v.y), pack_h2(v.z, v.w));
}

// ---------------------------------------------------------------------------
// mma.sync fp16 2-term GEMM: C[128 x 64 per block] = (Ah+Al) * Wh^T + bias
// 256 threads = 8 warps (4 m-warps x 2 n-warps), warp tile 32x32.
// Dyn-static smem: double buffer 20KB: Ahi 8K | Alo 8K | Whi 4K.
// ---------------------------------------------------------------------------
template <bool SPLIT>
__device__ __forceinline__ void gemm_mma_core(
    const __half* __restrict__ Ahi, const __half* __restrict__ Alo,
    const __half* __restrict__ Whi,
    const float* __restrict__ bias, float* __restrict__ Cf,
    __half* __restrict__ Chi)
{
    __shared__ char smbuf[40960];   // 2 x 20480
    const int tid = threadIdx.x, lane = tid & 31, wid = tid >> 5;
    const int warpM = wid & 3, warpN = wid >> 2;
    const int row0 = blockIdx.y * 128, col0 = blockIdx.x * 64;
    const uint32_t sb = smem_u32(smbuf);

    const int grow = tid >> 2, gch = tid & 3;
    const size_t aoff0 = (size_t)(row0 + grow) * (DMODEL * 2) + gch * 16;
    const size_t aoff1 = aoff0 + (size_t)64 * (DMODEL * 2);
    const size_t woff  = (size_t)(col0 + grow) * (DMODEL * 2) + gch * 16;
    const uint32_t dA0 = SWB(grow, gch);
    const uint32_t dA1 = SWB(grow + 64, gch);
    const uint32_t dW  = SWB(grow, gch);

    float acc[2][4][4];
#pragma unroll
    for (int mt = 0; mt < 2; mt++)
#pragma unroll
        for (int nt = 0; nt < 4; nt++)
#pragma unroll
            for (int e = 0; e < 4; e++) acc[mt][nt][e] = 0.f;

    uint4 pre[5];
    pre[0] = *(const uint4*)((const char*)Ahi + aoff0);
    pre[1] = *(const uint4*)((const char*)Ahi + aoff1);
    pre[2] = *(const uint4*)((const char*)Alo + aoff0);
    pre[3] = *(const uint4*)((const char*)Alo + aoff1);
    pre[4] = *(const uint4*)((const char*)Whi + woff);

    const int arowl = warpM * 32 + (lane & 7) + ((lane >> 3) & 1) * 8;
    const int achl  = (lane >> 4) & 1;
    const int browl = warpN * 32 + (lane & 7) + ((lane >> 4) & 1) * 8;
    const int bchl  = (lane >> 3) & 1;

    int buf = 0;
    for (int c = 0; c < 32; c++) {
        char* base = smbuf + buf * 20480;
        *(uint4*)(base + 0     + dA0) = pre[0];
        *(uint4*)(base + 0     + dA1) = pre[1];
        *(uint4*)(base + 8192  + dA0) = pre[2];
        *(uint4*)(base + 8192  + dA1) = pre[3];
        *(uint4*)(base + 16384 + dW)  = pre[4];
        __syncthreads();

        if (c + 1 < 32) {
            const size_t cb = (size_t)(c + 1) * 64;
            pre[0] = *(const uint4*)((const char*)Ahi + aoff0 + cb);
            pre[1] = *(const uint4*)((const char*)Ahi + aoff1 + cb);
            pre[2] = *(const uint4*)((const char*)Alo + aoff0 + cb);
            pre[3] = *(const uint4*)((const char*)Alo + aoff1 + cb);
            pre[4] = *(const uint4*)((const char*)Whi + woff + cb);
        }

        const uint32_t bb = sb + buf * 20480;
#pragma unroll
        for (int ks = 0; ks < 2; ks++) {
            uint32_t a_hi[2][4], a_lo[2][4], b_hi[2][4];
#pragma unroll
            for (int mt = 0; mt < 2; mt++) {
                const uint32_t ao = SWB(arowl + mt * 16, ks * 2 + achl);
                ldsm4(a_hi[mt], bb + 0    + ao);
                ldsm4(a_lo[mt], bb + 8192 + ao);
            }
#pragma unroll
            for (int np = 0; np < 2; np++) {
                const uint32_t bo = SWB(browl + np * 16, ks * 2 + bchl);
                ldsm4(b_hi[np], bb + 16384 + bo);
            }
#pragma unroll
            for (int mt = 0; mt < 2; mt++)
#pragma unroll
                for (int nt = 0; nt < 4; nt++) {
                    const uint32_t* bh = &b_hi[nt >> 1][(nt & 1) * 2];
                    mma_f16(acc[mt][nt], a_hi[mt], bh);
                    mma_f16(acc[mt][nt], a_lo[mt], bh);
                }
        }
        buf ^= 1;
    }

#pragma unroll
    for (int mt = 0; mt < 2; mt++) {
        const int r = row0 + warpM * 32 + mt * 16 + (lane >> 2);
#pragma unroll
        for (int nt = 0; nt < 4; nt++) {
            const int col = col0 + warpN * 32 + nt * 8 + (lane & 3) * 2;
            const float b0 = bias[col], b1 = bias[col + 1];
            const float o0 = acc[mt][nt][0] + b0, o1 = acc[mt][nt][1] + b1;
            const float o2 = acc[mt][nt][2] + b0, o3 = acc[mt][nt][3] + b1;
            if (SPLIT) {
                *(uint32_t*)&Chi[(size_t)r * DMODEL + col]       = pack_h2(o0, o1);
                *(uint32_t*)&Chi[(size_t)(r + 8) * DMODEL + col] = pack_h2(o2, o3);
            } else {
                *(float2*)&Cf[(size_t)r * DMODEL + col]       = make_float2(o0, o1);
                *(float2*)&Cf[(size_t)(r + 8) * DMODEL + col] = make_float2(o2, o3);
            }
        }
    }
}

__global__ void __launch_bounds__(256, 2) qkv_mma(
    const float* __restrict__ bq, const float* __restrict__ bk, const float* __restrict__ bv)
{
    const int z = blockIdx.z;
    const float* bias = (z == 0) ? bq : (z == 1) ? bk : bv;
    gemm_mma_core<true>(g_hiX + z * NX, g_loX + z * NX, g_hiW + z * NW, bias,
                        nullptr, g_hiQKV + z * NX);
}

__global__ void __launch_bounds__(256, 2) out_mma(
    const float* __restrict__ bo, float* __restrict__ C)
{
    gemm_mma_core<false>(g_hiC, g_loC, g_hiW + 3 * NW, bo, C, nullptr);
}

// ---------------------------------------------------------------------------
// Fused flash attention, fp16 1-term MMAs. Pass 1: QK^T -> rowsums.
// Pass 2: identical QK^T -> exp*rinv -> write attn -> PV (P_hi, V_hi) -> ctx.
// Smem: Qhi 16K | Khi 8K | Vhi 8K | rsum 512
// ---------------------------------------------------------------------------
#define ATT_SMEM (32768 + 512)

__global__ void __launch_bounds__(256) attn_fused(float* __restrict__ attn)
{
    extern __shared__ char sm[];
    const uint32_t sQh = smem_u32(sm);
    const uint32_t sKh = sQh + 16384;
    const uint32_t sVh = sQh + 24576;
    float* rsum = (float*)(sm + 32768);

    const int tid = threadIdx.x, lane = tid & 31, wid = tid >> 5;
    const int warpM = wid & 3, warpN = wid >> 2;
    const int p = blockIdx.y, bb = p >> 4, h = p & 15;
    const int row0 = blockIdx.x * 128;

#pragma unroll
    for (int ps = 0; ps < 4; ps++) {
        const int u = tid + ps * 256;
        const int row = u >> 3, ch = u & 7;
        const size_t ge = (size_t)(bb * S_LEN + row0 + row) * DMODEL + h * HDIM + ch * 8;
        *(uint4*)(sm + SWB128(row, ch)) = *(const uint4*)(g_hiQKV + ge);
    }
    if (tid < 128) rsum[tid] = 0.f;

    const int arowl = warpM * 32 + (lane & 7) + ((lane >> 3) & 1) * 8;
    const int achl  = (lane >> 4) & 1;
    const int browl = warpN * 32 + (lane & 7) + ((lane >> 4) & 1) * 8;
    const int bchl  = (lane >> 3) & 1;
    const int vrowl = (lane & 7) + ((lane >> 3) & 1) * 8;
    const int vtog  = (lane >> 4) & 1;
    const float sc = 0.125f;

    // ---------------- pass 1: rowsums ----------------
    float rs[4] = {0.f, 0.f, 0.f, 0.f};
    for (int c = 0; c < 32; c++) {
        const int c0 = c * 64;
        __syncthreads();
#pragma unroll
        for (int ps = 0; ps < 2; ps++) {
            const int u = tid + ps * 256;
            const int row = u >> 3, ch = u & 7;
            const size_t ge = NX + (size_t)(bb * S_LEN + c0 + row) * DMODEL + h * HDIM + ch * 8;
            *(uint4*)(sm + 16384 + SWB128(row, ch)) = *(const uint4*)(g_hiQKV + ge);
        }
        __syncthreads();

        float acc[2][4][4];
#pragma unroll
        for (int mt = 0; mt < 2; mt++)
#pragma unroll
            for (int nt = 0; nt < 4; nt++)
#pragma unroll
                for (int e = 0; e < 4; e++) acc[mt][nt][e] = 0.f;
#pragma unroll
        for (int ks = 0; ks < 4; ks++) {
            uint32_t a_hi[2][4], b_hi[2][4];
#pragma unroll
            for (int mt = 0; mt < 2; mt++)
                ldsm4(a_hi[mt], sQh + SWB128(arowl + mt * 16, ks * 2 + achl));
#pragma unroll
            for (int np = 0; np < 2; np++)
                ldsm4(b_hi[np], sKh + SWB128(browl + np * 16, ks * 2 + bchl));
#pragma unroll
            for (int mt = 0; mt < 2; mt++)
#pragma unroll
                for (int nt = 0; nt < 4; nt++)
                    mma_f16(acc[mt][nt], a_hi[mt], &b_hi[nt >> 1][(nt & 1) * 2]);
        }
#pragma unroll
        for (int mt = 0; mt < 2; mt++)
#pragma unroll
            for (int nt = 0; nt < 4; nt++) {
                rs[mt * 2 + 0] += __expf(acc[mt][nt][0] * sc) + __expf(acc[mt][nt][1] * sc);
                rs[mt * 2 + 1] += __expf(acc[mt][nt][2] * sc) + __expf(acc[mt][nt][3] * sc);
            }
    }
#pragma unroll
    for (int i = 0; i < 4; i++) {
        rs[i] += __shfl_xor_sync(0xffffffffu, rs[i], 1);
        rs[i] += __shfl_xor_sync(0xffffffffu, rs[i], 2);
    }
    if ((lane & 3) == 0) {
#pragma unroll
        for (int mt = 0; mt < 2; mt++) {
            atomicAdd(&rsum[warpM * 32 + mt * 16 + (lane >> 2)],     rs[mt * 2 + 0]);
            atomicAdd(&rsum[warpM * 32 + mt * 16 + (lane >> 2) + 8], rs[mt * 2 + 1]);
        }
    }
    __syncthreads();
    if (tid < 128) rsum[tid] = 1.0f / rsum[tid];
    __syncthreads();
    float rinv[2][2];
#pragma unroll
    for (int mt = 0; mt < 2; mt++) {
        rinv[mt][0] = rsum[warpM * 32 + mt * 16 + (lane >> 2)];
        rinv[mt][1] = rsum[warpM * 32 + mt * 16 + (lane >> 2) + 8];
    }

    // ---------------- pass 2: attn write + PV ----------------
    float ctx[2][8][4];
#pragma unroll
    for (int mt = 0; mt < 2; mt++)
#pragma unroll
        for (int nt = 0; nt < 8; nt++)
#pragma unroll
            for (int e = 0; e < 4; e++) ctx[mt][nt][e] = 0.f;

    for (int c = 0; c < 32; c++) {
        const int c0 = c * 64;
        __syncthreads();
#pragma unroll
        for (int ps = 0; ps < 2; ps++) {
            const int u = tid + ps * 256;
            const int row = u >> 3, ch = u & 7;
            const uint32_t so = SWB128(row, ch);
            const size_t geK = NX     + (size_t)(bb * S_LEN + c0 + row) * DMODEL + h * HDIM + ch * 8;
            const size_t geV = 2 * NX + (size_t)(bb * S_LEN + c0 + row) * DMODEL + h * HDIM + ch * 8;
            *(uint4*)(sm + 16384 + so) = *(const uint4*)(g_hiQKV + geK);
            *(uint4*)(sm + 24576 + so) = *(const uint4*)(g_hiQKV + geV);
        }
        __syncthreads();

        float acc[2][4][4];
#pragma unroll
        for (int mt = 0; mt < 2; mt++)
#pragma unroll
            for (int nt = 0; nt < 4; nt++)
#pragma unroll
                for (int e = 0; e < 4; e++) acc[mt][nt][e] = 0.f;
#pragma unroll
        for (int ks = 0; ks < 4; ks++) {
            uint32_t a_hi[2][4], b_hi[2][4];
#pragma unroll
            for (int mt = 0; mt < 2; mt++)
                ldsm4(a_hi[mt], sQh + SWB128(arowl + mt * 16, ks * 2 + achl));
#pragma unroll
            for (int np = 0; np < 2; np++)
                ldsm4(b_hi[np], sKh + SWB128(browl + np * 16, ks * 2 + bchl));
#pragma unroll
            for (int mt = 0; mt < 2; mt++)
#pragma unroll
                for (int nt = 0; nt < 4; nt++)
                    mma_f16(acc[mt][nt], a_hi[mt], &b_hi[nt >> 1][(nt & 1) * 2]);
        }

#pragma unroll
        for (int mt = 0; mt < 2; mt++) {
            const int r = row0 + warpM * 32 + mt * 16 + (lane >> 2);
#pragma unroll
            for (int nt = 0; nt < 4; nt++) {
                const int col = c0 + warpN * 32 + nt * 8 + (lane & 3) * 2;
                const float p0 = __expf(acc[mt][nt][0] * sc) * rinv[mt][0];
                const float p1 = __expf(acc[mt][nt][1] * sc) * rinv[mt][0];
                const float p2 = __expf(acc[mt][nt][2] * sc) * rinv[mt][1];
                const float p3 = __expf(acc[mt][nt][3] * sc) * rinv[mt][1];
                const size_t gi = ((size_t)(p * S_LEN) + r) * S_LEN + col;
                *(float2*)&attn[gi]             = make_float2(p0, p1);
                *(float2*)&attn[gi + 8 * S_LEN] = make_float2(p2, p3);
                acc[mt][nt][0] = p0; acc[mt][nt][1] = p1;
                acc[mt][nt][2] = p2; acc[mt][nt][3] = p3;
            }
        }

        // PV: this warp handles its 32 keys (2 groups of 16), full hd=64
#pragma unroll
        for (int kg = 0; kg < 2; kg++) {
            uint32_t ah[2][4];
#pragma unroll
            for (int mt = 0; mt < 2; mt++) {
                ah[mt][0] = pack_h2(acc[mt][2 * kg][0],     acc[mt][2 * kg][1]);
                ah[mt][1] = pack_h2(acc[mt][2 * kg][2],     acc[mt][2 * kg][3]);
                ah[mt][2] = pack_h2(acc[mt][2 * kg + 1][0], acc[mt][2 * kg + 1][1]);
                ah[mt][3] = pack_h2(acc[mt][2 * kg + 1][2], acc[mt][2 * kg + 1][3]);
            }
            uint32_t bh[4][4];
            const int kb = warpN * 32 + kg * 16;
#pragma unroll
            for (int ld = 0; ld < 4; ld++)
                ldsm4t(bh[ld], sVh + SWB128(kb + vrowl, ld * 2 + vtog));
#pragma unroll
            for (int mt = 0; mt < 2; mt++)
#pragma unroll
                for (int nt = 0; nt < 8; nt++)
                    mma_f16(ctx[mt][nt], ah[mt], &bh[nt >> 1][(nt & 1) * 2]);
        }
    }

    // cross-warpN ctx reduction via smem (reuse Q region: 128x64 fp32 = 32KB)
    __syncthreads();
    float* red = (float*)sm;
    if (warpN == 1) {
#pragma unroll
        for (int mt = 0; mt < 2; mt++) {
            const int rl = warpM * 32 + mt * 16 + (lane >> 2);
#pragma unroll
            for (int nt = 0; nt < 8; nt++) {
                const int col = nt * 8 + (lane & 3) * 2;
                *(float2*)&red[rl * 64 + col]       = make_float2(ctx[mt][nt][0], ctx[mt][nt][1]);
                *(float2*)&red[(rl + 8) * 64 + col] = make_float2(ctx[mt][nt][2], ctx[mt][nt][3]);
            }
        }
    }
    __syncthreads();
    if (warpN == 0) {
#pragma unroll
        for (int mt = 0; mt < 2; mt++) {
            const int rl = warpM * 32 + mt * 16 + (lane >> 2);
            const size_t gr0 = (size_t)(bb * S_LEN + row0 + rl) * DMODEL + h * HDIM;
            const size_t gr1 = gr0 + (size_t)8 * DMODEL;
#pragma unroll
            for (int nt = 0; nt < 8; nt++) {
                const int col = nt * 8 + (lane & 3) * 2;
                float2 s0 = *(float2*)&red[rl * 64 + col];
                float2 s1 = *(float2*)&red[(rl + 8) * 64 + col];
                const float o0 = ctx[mt][nt][0] + s0.x, o1 = ctx[mt][nt][1] + s0.y;
                const float o2 = ctx[mt][nt][2] + s1.x, o3 = ctx[mt][nt][3] + s1.y;
                uint32_t h01, l01, h23, l23;
                split_pair(o0, o1, h01, l01);
                split_pair(o2, o3, h23, l23);
                *(uint32_t*)&g_hiC[gr0 + col] = h01;
                *(uint32_t*)&g_loC[gr0 + col] = l01;
                *(uint32_t*)&g_hiC[gr1 + col] = h23;
                *(uint32_t*)&g_loC[gr1 + col] = l23;
            }
        }
    }
}

// ---------------------------------------------------------------------------
extern "C" void kernel_launch(void* const* d_in, const int* in_sizes, int n_in,
                              void* d_out, int out_size) {
    const float* query = (const float*)d_in[0];
    const float* key_  = (const float*)d_in[1];
    const float* value = (const float*)d_in[2];
    const float* Wq = (const float*)d_in[3];
    const float* bq = (const float*)d_in[4];
    const float* Wk = (const float*)d_in[5];
    const float* bk = (const float*)d_in[6];
    const float* Wv = (const float*)d_in[7];
    const float* bv = (const float*)d_in[8];
    const float* Wo = (const float*)d_in[9];
    const float* bo = (const float*)d_in[10];

    float* outp = (float*)d_out;
    float* attn = outp + NX;          // tuple output: (out, attn)

    static int attr_set = 0;
    if (!attr_set) {
        cudaFuncSetAttribute(attn_fused, cudaFuncAttributeMaxDynamicSharedMemorySize, ATT_SMEM);
        attr_set = 1;
    }

    __half *hiX, *loX, *hiW;
    cudaGetSymbolAddress((void**)&hiX, g_hiX);
    cudaGetSymbolAddress((void**)&loX, g_loX);
    cudaGetSymbolAddress((void**)&hiW, g_hiW);

    conv_split<<<NX / 1024, 256>>>(query, hiX, loX);
    conv_split<<<NX / 1024, 256>>>(key_,  hiX + NX, loX + NX);
    conv_split<<<NX / 1024, 256>>>(value, hiX + 2 * NX, loX + 2 * NX);
    conv_hi<<<NW / 1024, 256>>>(Wq, hiW);
    conv_hi<<<NW / 1024, 256>>>(Wk, hiW + NW);
    conv_hi<<<NW / 1024, 256>>>(Wv, hiW + 2 * NW);
    conv_hi<<<NW / 1024, 256>>>(Wo, hiW + 3 * NW);

    qkv_mma<<<dim3(DMODEL / 64, MROWS / 128, 3), 256>>>(bq, bk, bv);
    attn_fused<<<dim3(S_LEN / 128, NPAIRS), 256, ATT_SMEM>>>(attn);
    out_mma<<<dim3(DMODEL / 64, MROWS / 128), 256>>>(bo, outp);
}

// round 11
// speedup vs baseline: 1.3875x; 1.0782x over previous
#include <cuda_runtime.h>
#include <cuda_fp16.h>
#include <cstdint>

#define S_LEN  2048
#define DMODEL 1024
#define NHEAD  16
#define HDIM   64
#define MROWS  4096   // S*B
#define NPAIRS 32     // B*NHEAD
#define NX     ((size_t)MROWS * DMODEL)
#define NW     ((size_t)DMODEL * DMODEL)

// ---------------- scratch globals (allocation-free rule) ----------------
__device__ __half g_hiX[(size_t)3 * NX];    // converted q/k/v inputs (fp16 hi)
__device__ __half g_hiW[(size_t)4 * NW];    // converted Wq,Wk,Wv,Wo (hi)
__device__ __half g_hiQKV[(size_t)3 * NX];  // projected Q,K,V (fp16)
__device__ __half g_hiC[NX];                // attention context hi/lo
__device__ __half g_loC[NX];

// ---------------- helpers ----------------
__device__ __forceinline__ uint32_t smem_u32(const void* p) {
    uint32_t a;
    asm("{ .reg .u64 t; cvta.to.shared.u64 t, %1; cvt.u32.u64 %0, t; }" : "=r"(a) : "l"(p));
    return a;
}
__device__ __forceinline__ void ldsm4(uint32_t* r, uint32_t a) {
    asm volatile("ldmatrix.sync.aligned.m8n8.x4.shared.b16 {%0,%1,%2,%3}, [%4];"
        : "=r"(r[0]), "=r"(r[1]), "=r"(r[2]), "=r"(r[3]) : "r"(a));
}
__device__ __forceinline__ void ldsm4t(uint32_t* r, uint32_t a) {
    asm volatile("ldmatrix.sync.aligned.m8n8.x4.trans.shared.b16 {%0,%1,%2,%3}, [%4];"
        : "=r"(r[0]), "=r"(r[1]), "=r"(r[2]), "=r"(r[3]) : "r"(a));
}
__device__ __forceinline__ void mma_f16(float* d, const uint32_t* a, const uint32_t* b) {
    asm volatile("mma.sync.aligned.m16n8k16.row.col.f32.f16.f16.f32 "
        "{%0,%1,%2,%3},{%4,%5,%6,%7},{%8,%9},{%0,%1,%2,%3};"
        : "+f"(d[0]), "+f"(d[1]), "+f"(d[2]), "+f"(d[3])
        : "r"(a[0]), "r"(a[1]), "r"(a[2]), "r"(a[3]), "r"(b[0]), "r"(b[1]));
}
// 64B-row swizzle (GEMM tiles)
#define SWB(row, ch) (((row) << 6) + ((((ch) ^ (((row) >> 1) & 3))) << 4))
// 128B-row swizzle (attention tiles)
#define SWB128(row, ch) (((row) << 7) + ((((ch) ^ ((row) & 7))) << 4))

__device__ __forceinline__ void split_pair(float a, float b, uint32_t& hi, uint32_t& lo) {
    __half ha = __float2half(a), hb = __float2half(b);
    __half2 hp(ha, hb);
    __half2 lp(__float2half(a - __half2float(ha)),
               __float2half(b - __half2float(hb)));
    hi = *(uint32_t*)&hp;
    lo = *(uint32_t*)&lp;
}
__device__ __forceinline__ uint32_t pack_h2(float a, float b) {
    __half2 h = __floats2half2_rn(a, b);
    return *(uint32_t*)&h;
}

// ---------------- batched fp32 -> fp16 (hi) conversion ----------------
// tensors: 0..2 = q/k/v inputs (4M elems each -> 4096 blocks each),
//          3..6 = Wq,Wk,Wv,Wo (1M elems each -> 1024 blocks each)
struct ConvSrcs { const float* s[7]; };

__global__ void __launch_bounds__(256) conv_all(ConvSrcs p)
{
    const int b = blockIdx.x;
    int t; size_t eb;      // tensor id, element base of this block
    __half* dst;
    if (b < 12288) {
        t = b >> 12;
        eb = (size_t)(b & 4095) * 1024;
        dst = g_hiX + (size_t)t * NX;
    } else {
        const int w = b - 12288;
        t = 3 + (w >> 10);
        eb = (size_t)(w & 1023) * 1024;
        dst = g_hiW + (size_t)(t - 3) * NW;
    }
    const size_t i = eb + (size_t)threadIdx.x * 4;
    float4 v = *(const float4*)(p.s[t] + i);
    *(uint2*)(dst + i) = make_uint2(pack_h2(v.x, v.y), pack_h2(v.z, v.w));
}

// ---------------------------------------------------------------------------
// mma.sync fp16 GEMM: C[128 x 64 per block] = (Ah [+Al]) * Wh^T + bias
// 256 threads = 8 warps (4 m-warps x 2 n-warps), warp tile 32x32.
// ALO=false: 1-term (A_hi only). ALO=true: 2-term (A hi+lo).
// ---------------------------------------------------------------------------
template <bool SPLIT, bool ALO>
__device__ __forceinline__ void gemm_mma_core(
    const __half* __restrict__ Ahi, const __half* __restrict__ Alo,
    const __half* __restrict__ Whi,
    const float* __restrict__ bias, float* __restrict__ Cf,
    __half* __restrict__ Chi)
{
    constexpr int ALO_OFF = 8192;
    constexpr int W_OFF   = ALO ? 16384 : 8192;
    constexpr int BUFSZ   = ALO ? 20480 : 12288;
    __shared__ char smbuf[2 * BUFSZ];
    const int tid = threadIdx.x, lane = tid & 31, wid = tid >> 5;
    const int warpM = wid & 3, warpN = wid >> 2;
    const int row0 = blockIdx.y * 128, col0 = blockIdx.x * 64;
    const uint32_t sb = smem_u32(smbuf);

    const int grow = tid >> 2, gch = tid & 3;
    const size_t aoff0 = (size_t)(row0 + grow) * (DMODEL * 2) + gch * 16;
    const size_t aoff1 = aoff0 + (size_t)64 * (DMODEL * 2);
    const size_t woff  = (size_t)(col0 + grow) * (DMODEL * 2) + gch * 16;
    const uint32_t dA0 = SWB(grow, gch);
    const uint32_t dA1 = SWB(grow + 64, gch);
    const uint32_t dW  = SWB(grow, gch);

    float acc[2][4][4];
#pragma unroll
    for (int mt = 0; mt < 2; mt++)
#pragma unroll
        for (int nt = 0; nt < 4; nt++)
#pragma unroll
            for (int e = 0; e < 4; e++) acc[mt][nt][e] = 0.f;

    uint4 pre[5];
    pre[0] = *(const uint4*)((const char*)Ahi + aoff0);
    pre[1] = *(const uint4*)((const char*)Ahi + aoff1);
    pre[2] = *(const uint4*)((const char*)Whi + woff);
    if (ALO) {
        pre[3] = *(const uint4*)((const char*)Alo + aoff0);
        pre[4] = *(const uint4*)((const char*)Alo + aoff1);
    }

    const int arowl = warpM * 32 + (lane & 7) + ((lane >> 3) & 1) * 8;
    const int achl  = (lane >> 4) & 1;
    const int browl = warpN * 32 + (lane & 7) + ((lane >> 4) & 1) * 8;
    const int bchl  = (lane >> 3) & 1;

    int buf = 0;
    for (int c = 0; c < 32; c++) {
        char* base = smbuf + buf * BUFSZ;
        *(uint4*)(base + 0     + dA0) = pre[0];
        *(uint4*)(base + 0     + dA1) = pre[1];
        *(uint4*)(base + W_OFF + dW)  = pre[2];
        if (ALO) {
            *(uint4*)(base + ALO_OFF + dA0) = pre[3];
            *(uint4*)(base + ALO_OFF + dA1) = pre[4];
        }
        __syncthreads();

        if (c + 1 < 32) {
            const size_t cb = (size_t)(c + 1) * 64;
            pre[0] = *(const uint4*)((const char*)Ahi + aoff0 + cb);
            pre[1] = *(const uint4*)((const char*)Ahi + aoff1 + cb);
            pre[2] = *(const uint4*)((const char*)Whi + woff + cb);
            if (ALO) {
                pre[3] = *(const uint4*)((const char*)Alo + aoff0 + cb);
                pre[4] = *(const uint4*)((const char*)Alo + aoff1 + cb);
            }
        }

        const uint32_t bb = sb + buf * BUFSZ;
#pragma unroll
        for (int ks = 0; ks < 2; ks++) {
            uint32_t a_hi[2][4], a_lo[2][4], b_hi[2][4];
#pragma unroll
            for (int mt = 0; mt < 2; mt++) {
                const uint32_t ao = SWB(arowl + mt * 16, ks * 2 + achl);
                ldsm4(a_hi[mt], bb + 0 + ao);
                if (ALO) ldsm4(a_lo[mt], bb + ALO_OFF + ao);
            }
#pragma unroll
            for (int np = 0; np < 2; np++) {
                const uint32_t bo = SWB(browl + np * 16, ks * 2 + bchl);
                ldsm4(b_hi[np], bb + W_OFF + bo);
            }
#pragma unroll
            for (int mt = 0; mt < 2; mt++)
#pragma unroll
                for (int nt = 0; nt < 4; nt++) {
                    const uint32_t* bh = &b_hi[nt >> 1][(nt & 1) * 2];
                    mma_f16(acc[mt][nt], a_hi[mt], bh);
                    if (ALO) mma_f16(acc[mt][nt], a_lo[mt], bh);
                }
        }
        buf ^= 1;
    }

#pragma unroll
    for (int mt = 0; mt < 2; mt++) {
        const int r = row0 + warpM * 32 + mt * 16 + (lane >> 2);
#pragma unroll
        for (int nt = 0; nt < 4; nt++) {
            const int col = col0 + warpN * 32 + nt * 8 + (lane & 3) * 2;
            const float b0 = bias[col], b1 = bias[col + 1];
            const float o0 = acc[mt][nt][0] + b0, o1 = acc[mt][nt][1] + b1;
            const float o2 = acc[mt][nt][2] + b0, o3 = acc[mt][nt][3] + b1;
            if (SPLIT) {
                *(uint32_t*)&Chi[(size_t)r * DMODEL + col]       = pack_h2(o0, o1);
                *(uint32_t*)&Chi[(size_t)(r + 8) * DMODEL + col] = pack_h2(o2, o3);
            } else {
                *(float2*)&Cf[(size_t)r * DMODEL + col]       = make_float2(o0, o1);
                *(float2*)&Cf[(size_t)(r + 8) * DMODEL + col] = make_float2(o2, o3);
            }
        }
    }
}

__global__ void __launch_bounds__(256, 2) qkv_mma(
    const float* __restrict__ bq, const float* __restrict__ bk, const float* __restrict__ bv)
{
    const int z = blockIdx.z;
    const float* bias = (z == 0) ? bq : (z == 1) ? bk : bv;
    gemm_mma_core<true, false>(g_hiX + z * NX, nullptr, g_hiW + z * NW, bias,
                               nullptr, g_hiQKV + z * NX);
}

__global__ void __launch_bounds__(256, 2) out_mma(
    const float* __restrict__ bo, float* __restrict__ C)
{
    gemm_mma_core<false, true>(g_hiC, g_loC, g_hiW + 3 * NW, bo, C, nullptr);
}

// ---------------------------------------------------------------------------
// Fused flash attention, fp16 1-term MMAs (unchanged from R10, passing).
// Pass 1: QK^T -> rowsums.  Pass 2: identical QK^T -> exp*rinv -> write attn
// -> PV -> ctx (hi/lo).
// Smem: Qhi 16K | Khi 8K | Vhi 8K | rsum 512
// ---------------------------------------------------------------------------
#define ATT_SMEM (32768 + 512)

__global__ void __launch_bounds__(256) attn_fused(float* __restrict__ attn)
{
    extern __shared__ char sm[];
    const uint32_t sQh = smem_u32(sm);
    const uint32_t sKh = sQh + 16384;
    const uint32_t sVh = sQh + 24576;
    float* rsum = (float*)(sm + 32768);

    const int tid = threadIdx.x, lane = tid & 31, wid = tid >> 5;
    const int warpM = wid & 3, warpN = wid >> 2;
    const int p = blockIdx.y, bb = p >> 4, h = p & 15;
    const int row0 = blockIdx.x * 128;

#pragma unroll
    for (int ps = 0; ps < 4; ps++) {
        const int u = tid + ps * 256;
        const int row = u >> 3, ch = u & 7;
        const size_t ge = (size_t)(bb * S_LEN + row0 + row) * DMODEL + h * HDIM + ch * 8;
        *(uint4*)(sm + SWB128(row, ch)) = *(const uint4*)(g_hiQKV + ge);
    }
    if (tid < 128) rsum[tid] = 0.f;

    const int arowl = warpM * 32 + (lane & 7) + ((lane >> 3) & 1) * 8;
    const int achl  = (lane >> 4) & 1;
    const int browl = warpN * 32 + (lane & 7) + ((lane >> 4) & 1) * 8;
    const int bchl  = (lane >> 3) & 1;
    const int vrowl = (lane & 7) + ((lane >> 3) & 1) * 8;
    const int vtog  = (lane >> 4) & 1;
    const float sc = 0.125f;

    // ---------------- pass 1: rowsums ----------------
    float rs[4] = {0.f, 0.f, 0.f, 0.f};
    for (int c = 0; c < 32; c++) {
        const int c0 = c * 64;
        __syncthreads();
#pragma unroll
        for (int ps = 0; ps < 2; ps++) {
            const int u = tid + ps * 256;
            const int row = u >> 3, ch = u & 7;
            const size_t ge = NX + (size_t)(bb * S_LEN + c0 + row) * DMODEL + h * HDIM + ch * 8;
            *(uint4*)(sm + 16384 + SWB128(row, ch)) = *(const uint4*)(g_hiQKV + ge);
        }
        __syncthreads();

        float acc[2][4][4];
#pragma unroll
        for (int mt = 0; mt < 2; mt++)
#pragma unroll
            for (int nt = 0; nt < 4; nt++)
#pragma unroll
                for (int e = 0; e < 4; e++) acc[mt][nt][e] = 0.f;
#pragma unroll
        for (int ks = 0; ks < 4; ks++) {
            uint32_t a_hi[2][4], b_hi[2][4];
#pragma unroll
            for (int mt = 0; mt < 2; mt++)
                ldsm4(a_hi[mt], sQh + SWB128(arowl + mt * 16, ks * 2 + achl));
#pragma unroll
            for (int np = 0; np < 2; np++)
                ldsm4(b_hi[np], sKh + SWB128(browl + np * 16, ks * 2 + bchl));
#pragma unroll
            for (int mt = 0; mt < 2; mt++)
#pragma unroll
                for (int nt = 0; nt < 4; nt++)
                    mma_f16(acc[mt][nt], a_hi[mt], &b_hi[nt >> 1][(nt & 1) * 2]);
        }
#pragma unroll
        for (int mt = 0; mt < 2; mt++)
#pragma unroll
            for (int nt = 0; nt < 4; nt++) {
                rs[mt * 2 + 0] += __expf(acc[mt][nt][0] * sc) + __expf(acc[mt][nt][1] * sc);
                rs[mt * 2 + 1] += __expf(acc[mt][nt][2] * sc) + __expf(acc[mt][nt][3] * sc);
            }
    }
#pragma unroll
    for (int i = 0; i < 4; i++) {
        rs[i] += __shfl_xor_sync(0xffffffffu, rs[i], 1);
        rs[i] += __shfl_xor_sync(0xffffffffu, rs[i], 2);
    }
    if ((lane & 3) == 0) {
#pragma unroll
        for (int mt = 0; mt < 2; mt++) {
            atomicAdd(&rsum[warpM * 32 + mt * 16 + (lane >> 2)],     rs[mt * 2 + 0]);
            atomicAdd(&rsum[warpM * 32 + mt * 16 + (lane >> 2) + 8], rs[mt * 2 + 1]);
        }
    }
    __syncthreads();
    if (tid < 128) rsum[tid] = 1.0f / rsum[tid];
    __syncthreads();
    float rinv[2][2];
#pragma unroll
    for (int mt = 0; mt < 2; mt++) {
        rinv[mt][0] = rsum[warpM * 32 + mt * 16 + (lane >> 2)];
        rinv[mt][1] = rsum[warpM * 32 + mt * 16 + (lane >> 2) + 8];
    }

    // ---------------- pass 2: attn write + PV ----------------
    float ctx[2][8][4];
#pragma unroll
    for (int mt = 0; mt < 2; mt++)
#pragma unroll
        for (int nt = 0; nt < 8; nt++)
#pragma unroll
            for (int e = 0; e < 4; e++) ctx[mt][nt][e] = 0.f;

    for (int c = 0; c < 32; c++) {
        const int c0 = c * 64;
        __syncthreads();
#pragma unroll
        for (int ps = 0; ps < 2; ps++) {
            const int u = tid + ps * 256;
            const int row = u >> 3, ch = u & 7;
            const uint32_t so = SWB128(row, ch);
            const size_t geK = NX     + (size_t)(bb * S_LEN + c0 + row) * DMODEL + h * HDIM + ch * 8;
            const size_t geV = 2 * NX + (size_t)(bb * S_LEN + c0 + row) * DMODEL + h * HDIM + ch * 8;
            *(uint4*)(sm + 16384 + so) = *(const uint4*)(g_hiQKV + geK);
            *(uint4*)(sm + 24576 + so) = *(const uint4*)(g_hiQKV + geV);
        }
        __syncthreads();

        float acc[2][4][4];
#pragma unroll
        for (int mt = 0; mt < 2; mt++)
#pragma unroll
            for (int nt = 0; nt < 4; nt++)
#pragma unroll
                for (int e = 0; e < 4; e++) acc[mt][nt][e] = 0.f;
#pragma unroll
        for (int ks = 0; ks < 4; ks++) {
            uint32_t a_hi[2][4], b_hi[2][4];
#pragma unroll
            for (int mt = 0; mt < 2; mt++)
                ldsm4(a_hi[mt], sQh + SWB128(arowl + mt * 16, ks * 2 + achl));
#pragma unroll
            for (int np = 0; np < 2; np++)
                ldsm4(b_hi[np], sKh + SWB128(browl + np * 16, ks * 2 + bchl));
#pragma unroll
            for (int mt = 0; mt < 2; mt++)
#pragma unroll
                for (int nt = 0; nt < 4; nt++)
                    mma_f16(acc[mt][nt], a_hi[mt], &b_hi[nt >> 1][(nt & 1) * 2]);
        }

#pragma unroll
        for (int mt = 0; mt < 2; mt++) {
            const int r = row0 + warpM * 32 + mt * 16 + (lane >> 2);
#pragma unroll
            for (int nt = 0; nt < 4; nt++) {
                const int col = c0 + warpN * 32 + nt * 8 + (lane & 3) * 2;
                const float p0 = __expf(acc[mt][nt][0] * sc) * rinv[mt][0];
                const float p1 = __expf(acc[mt][nt][1] * sc) * rinv[mt][0];
                const float p2 = __expf(acc[mt][nt][2] * sc) * rinv[mt][1];
                const float p3 = __expf(acc[mt][nt][3] * sc) * rinv[mt][1];
                const size_t gi = ((size_t)(p * S_LEN) + r) * S_LEN + col;
                *(float2*)&attn[gi]             = make_float2(p0, p1);
                *(float2*)&attn[gi + 8 * S_LEN] = make_float2(p2, p3);
                acc[mt][nt][0] = p0; acc[mt][nt][1] = p1;
                acc[mt][nt][2] = p2; acc[mt][nt][3] = p3;
            }
        }

        // PV: this warp handles its 32 keys (2 groups of 16), full hd=64
#pragma unroll
        for (int kg = 0; kg < 2; kg++) {
            uint32_t ah[2][4];
#pragma unroll
            for (int mt = 0; mt < 2; mt++) {
                ah[mt][0] = pack_h2(acc[mt][2 * kg][0],     acc[mt][2 * kg][1]);
                ah[mt][1] = pack_h2(acc[mt][2 * kg][2],     acc[mt][2 * kg][3]);
                ah[mt][2] = pack_h2(acc[mt][2 * kg + 1][0], acc[mt][2 * kg + 1][1]);
                ah[mt][3] = pack_h2(acc[mt][2 * kg + 1][2], acc[mt][2 * kg + 1][3]);
            }
            uint32_t bh[4][4];
            const int kb = warpN * 32 + kg * 16;
#pragma unroll
            for (int ld = 0; ld < 4; ld++)
                ldsm4t(bh[ld], sVh + SWB128(kb + vrowl, ld * 2 + vtog));
#pragma unroll
            for (int mt = 0; mt < 2; mt++)
#pragma unroll
                for (int nt = 0; nt < 8; nt++)
                    mma_f16(ctx[mt][nt], ah[mt], &bh[nt >> 1][(nt & 1) * 2]);
        }
    }

    // cross-warpN ctx reduction via smem (reuse Q region: 128x64 fp32 = 32KB)
    __syncthreads();
    float* red = (float*)sm;
    if (warpN == 1) {
#pragma unroll
        for (int mt = 0; mt < 2; mt++) {
            const int rl = warpM * 32 + mt * 16 + (lane >> 2);
#pragma unroll
            for (int nt = 0; nt < 8; nt++) {
                const int col = nt * 8 + (lane & 3) * 2;
                *(float2*)&red[rl * 64 + col]       = make_float2(ctx[mt][nt][0], ctx[mt][nt][1]);
                *(float2*)&red[(rl + 8) * 64 + col] = make_float2(ctx[mt][nt][2], ctx[mt][nt][3]);
            }
        }
    }
    __syncthreads();
    if (warpN == 0) {
#pragma unroll
        for (int mt = 0; mt < 2; mt++) {
            const int rl = warpM * 32 + mt * 16 + (lane >> 2);
            const size_t gr0 = (size_t)(bb * S_LEN + row0 + rl) * DMODEL + h * HDIM;
            const size_t gr1 = gr0 + (size_t)8 * DMODEL;
#pragma unroll
            for (int nt = 0; nt < 8; nt++) {
                const int col = nt * 8 + (lane & 3) * 2;
                float2 s0 = *(float2*)&red[rl * 64 + col];
                float2 s1 = *(float2*)&red[(rl + 8) * 64 + col];
                const float o0 = ctx[mt][nt][0] + s0.x, o1 = ctx[mt][nt][1] + s0.y;
                const float o2 = ctx[mt][nt][2] + s1.x, o3 = ctx[mt][nt][3] + s1.y;
                uint32_t h01, l01, h23, l23;
                split_pair(o0, o1, h01, l01);
                split_pair(o2, o3, h23, l23);
                *(uint32_t*)&g_hiC[gr0 + col] = h01;
                *(uint32_t*)&g_loC[gr0 + col] = l01;
                *(uint32_t*)&g_hiC[gr1 + col] = h23;
                *(uint32_t*)&g_loC[gr1 + col] = l23;
            }
        }
    }
}

// ---------------------------------------------------------------------------
extern "C" void kernel_launch(void* const* d_in, const int* in_sizes, int n_in,
                              void* d_out, int out_size) {
    const float* query = (const float*)d_in[0];
    const float* key_  = (const float*)d_in[1];
    const float* value = (const float*)d_in[2];
    const float* Wq = (const float*)d_in[3];
    const float* bq = (const float*)d_in[4];
    const float* Wk = (const float*)d_in[5];
    const float* bk = (const float*)d_in[6];
    const float* Wv = (const float*)d_in[7];
    const float* bv = (const float*)d_in[8];
    const float* Wo = (const float*)d_in[9];
    const float* bo = (const float*)d_in[10];

    float* outp = (float*)d_out;
    float* attn = outp + NX;          // tuple output: (out, attn)

    static int attr_set = 0;
    if (!attr_set) {
        cudaFuncSetAttribute(attn_fused, cudaFuncAttributeMaxDynamicSharedMemorySize, ATT_SMEM);
        attr_set = 1;
    }

    ConvSrcs cs;
    cs.s[0] = query; cs.s[1] = key_; cs.s[2] = value;
    cs.s[3] = Wq; cs.s[4] = Wk; cs.s[5] = Wv; cs.s[6] = Wo;
    conv_all<<<16384, 256>>>(cs);

    qkv_mma<<<dim3(DMODEL / 64, MROWS / 128, 3), 256>>>(bq, bk, bv);
    attn_fused<<<dim3(S_LEN / 128, NPAIRS), 256, ATT_SMEM>>>(attn);
    out_mma<<<dim3(DMODEL / 64, MROWS / 128), 256>>>(bo, outp);
}

// round 12
// speedup vs baseline: 1.6149x; 1.1639x over previous
#include <cuda_runtime.h>
#include <cuda_fp16.h>
#include <cstdint>

#define S_LEN  2048
#define DMODEL 1024
#define NHEAD  16
#define HDIM   64
#define MROWS  4096   // S*B
#define NPAIRS 32     // B*NHEAD
#define NX     ((size_t)MROWS * DMODEL)
#define NW     ((size_t)DMODEL * DMODEL)

// ---------------- scratch globals (allocation-free rule) ----------------
__device__ __half g_hiX[(size_t)3 * NX];    // converted q/k/v inputs (fp16 hi)
__device__ __half g_hiW[(size_t)4 * NW];    // converted Wq,Wk,Wv,Wo (hi)
__device__ __half g_hiQKV[(size_t)3 * NX];  // projected Q,K,V (fp16)
__device__ __half g_hiC[NX];                // attention context hi/lo
__device__ __half g_loC[NX];
__device__ __half g_expS[(size_t)NPAIRS * S_LEN * S_LEN];  // unnorm expS frags

// ---------------- helpers ----------------
__device__ __forceinline__ uint32_t smem_u32(const void* p) {
    uint32_t a;
    asm("{ .reg .u64 t; cvta.to.shared.u64 t, %1; cvt.u32.u64 %0, t; }" : "=r"(a) : "l"(p));
    return a;
}
__device__ __forceinline__ void ldsm4(uint32_t* r, uint32_t a) {
    asm volatile("ldmatrix.sync.aligned.m8n8.x4.shared.b16 {%0,%1,%2,%3}, [%4];"
        : "=r"(r[0]), "=r"(r[1]), "=r"(r[2]), "=r"(r[3]) : "r"(a));
}
__device__ __forceinline__ void ldsm4t(uint32_t* r, uint32_t a) {
    asm volatile("ldmatrix.sync.aligned.m8n8.x4.trans.shared.b16 {%0,%1,%2,%3}, [%4];"
        : "=r"(r[0]), "=r"(r[1]), "=r"(r[2]), "=r"(r[3]) : "r"(a));
}
__device__ __forceinline__ void mma_f16(float* d, const uint32_t* a, const uint32_t* b) {
    asm volatile("mma.sync.aligned.m16n8k16.row.col.f32.f16.f16.f32 "
        "{%0,%1,%2,%3},{%4,%5,%6,%7},{%8,%9},{%0,%1,%2,%3};"
        : "+f"(d[0]), "+f"(d[1]), "+f"(d[2]), "+f"(d[3])
        : "r"(a[0]), "r"(a[1]), "r"(a[2]), "r"(a[3]), "r"(b[0]), "r"(b[1]));
}
// 64B-row swizzle (GEMM tiles)
#define SWB(row, ch) (((row) << 6) + ((((ch) ^ (((row) >> 1) & 3))) << 4))
// 128B-row swizzle (attention tiles)
#define SWB128(row, ch) (((row) << 7) + ((((ch) ^ ((row) & 7))) << 4))

__device__ __forceinline__ void split_pair(float a, float b, uint32_t& hi, uint32_t& lo) {
    __half ha = __float2half(a), hb = __float2half(b);
    __half2 hp(ha, hb);
    __half2 lp(__float2half(a - __half2float(ha)),
               __float2half(b - __half2float(hb)));
    hi = *(uint32_t*)&hp;
    lo = *(uint32_t*)&lp;
}
__device__ __forceinline__ uint32_t pack_h2(float a, float b) {
    __half2 h = __floats2half2_rn(a, b);
    return *(uint32_t*)&h;
}

// ---------------- batched fp32 -> fp16 (hi) conversion ----------------
struct ConvSrcs { const float* s[7]; };

__global__ void __launch_bounds__(256) conv_all(ConvSrcs p)
{
    const int b = blockIdx.x;
    int t; size_t eb;
    __half* dst;
    if (b < 12288) {
        t = b >> 12;
        eb = (size_t)(b & 4095) * 1024;
        dst = g_hiX + (size_t)t * NX;
    } else {
        const int w = b - 12288;
        t = 3 + (w >> 10);
        eb = (size_t)(w & 1023) * 1024;
        dst = g_hiW + (size_t)(t - 3) * NW;
    }
    const size_t i = eb + (size_t)threadIdx.x * 4;
    float4 v = *(const float4*)(p.s[t] + i);
    *(uint2*)(dst + i) = make_uint2(pack_h2(v.x, v.y), pack_h2(v.z, v.w));
}

// ---------------------------------------------------------------------------
// mma.sync fp16 GEMM: C[128 x 128 per block] = (Ah [+Al]) * Wh^T + bias
// 256 threads = 8 warps (4 m-warps x 2 n-warps), warp tile 32x64.
// ---------------------------------------------------------------------------
template <bool SPLIT, bool ALO>
__device__ __forceinline__ void gemm_mma_core(
    const __half* __restrict__ Ahi, const __half* __restrict__ Alo,
    const __half* __restrict__ Whi,
    const float* __restrict__ bias, float* __restrict__ Cf,
    __half* __restrict__ Chi)
{
    constexpr int ALO_OFF = 8192;
    constexpr int W_OFF   = ALO ? 16384 : 8192;
    constexpr int BUFSZ   = ALO ? 24576 : 16384;
    __shared__ char smbuf[2 * BUFSZ];
    const int tid = threadIdx.x, lane = tid & 31, wid = tid >> 5;
    const int warpM = wid & 3, warpN = wid >> 2;
    const int row0 = blockIdx.y * 128, col0 = blockIdx.x * 128;
    const uint32_t sb = smem_u32(smbuf);

    const int grow = tid >> 2, gch = tid & 3;
    const size_t aoff0 = (size_t)(row0 + grow) * (DMODEL * 2) + gch * 16;
    const size_t aoff1 = aoff0 + (size_t)64 * (DMODEL * 2);
    const size_t woff0 = (size_t)(col0 + grow) * (DMODEL * 2) + gch * 16;
    const size_t woff1 = woff0 + (size_t)64 * (DMODEL * 2);
    const uint32_t d0 = SWB(grow, gch);
    const uint32_t d1 = SWB(grow + 64, gch);

    float acc[2][8][4];
#pragma unroll
    for (int mt = 0; mt < 2; mt++)
#pragma unroll
        for (int nt = 0; nt < 8; nt++)
#pragma unroll
            for (int e = 0; e < 4; e++) acc[mt][nt][e] = 0.f;

    uint4 pre[6];
    pre[0] = *(const uint4*)((const char*)Ahi + aoff0);
    pre[1] = *(const uint4*)((const char*)Ahi + aoff1);
    pre[2] = *(const uint4*)((const char*)Whi + woff0);
    pre[3] = *(const uint4*)((const char*)Whi + woff1);
    if (ALO) {
        pre[4] = *(const uint4*)((const char*)Alo + aoff0);
        pre[5] = *(const uint4*)((const char*)Alo + aoff1);
    }

    const int arowl = warpM * 32 + (lane & 7) + ((lane >> 3) & 1) * 8;
    const int achl  = (lane >> 4) & 1;
    const int brow8 = (lane & 7) + ((lane >> 4) & 1) * 8;   // + warpN*64 + np*16
    const int bchl  = (lane >> 3) & 1;

    int buf = 0;
    for (int c = 0; c < 32; c++) {
        char* base = smbuf + buf * BUFSZ;
        *(uint4*)(base + 0     + d0) = pre[0];
        *(uint4*)(base + 0     + d1) = pre[1];
        *(uint4*)(base + W_OFF + d0) = pre[2];
        *(uint4*)(base + W_OFF + d1) = pre[3];
        if (ALO) {
            *(uint4*)(base + ALO_OFF + d0) = pre[4];
            *(uint4*)(base + ALO_OFF + d1) = pre[5];
        }
        __syncthreads();

        if (c + 1 < 32) {
            const size_t cb = (size_t)(c + 1) * 64;
            pre[0] = *(const uint4*)((const char*)Ahi + aoff0 + cb);
            pre[1] = *(const uint4*)((const char*)Ahi + aoff1 + cb);
            pre[2] = *(const uint4*)((const char*)Whi + woff0 + cb);
            pre[3] = *(const uint4*)((const char*)Whi + woff1 + cb);
            if (ALO) {
                pre[4] = *(const uint4*)((const char*)Alo + aoff0 + cb);
                pre[5] = *(const uint4*)((const char*)Alo + aoff1 + cb);
            }
        }

        const uint32_t bb = sb + buf * BUFSZ;
#pragma unroll
        for (int ks = 0; ks < 2; ks++) {
            uint32_t a_hi[2][4], a_lo[2][4], b_hi[4][4];
#pragma unroll
            for (int mt = 0; mt < 2; mt++) {
                const uint32_t ao = SWB(arowl + mt * 16, ks * 2 + achl);
                ldsm4(a_hi[mt], bb + 0 + ao);
                if (ALO) ldsm4(a_lo[mt], bb + ALO_OFF + ao);
            }
#pragma unroll
            for (int np = 0; np < 4; np++) {
                const uint32_t bo = SWB(warpN * 64 + np * 16 + brow8, ks * 2 + bchl);
                ldsm4(b_hi[np], bb + W_OFF + bo);
            }
#pragma unroll
            for (int mt = 0; mt < 2; mt++)
#pragma unroll
                for (int nt = 0; nt < 8; nt++) {
                    const uint32_t* bh = &b_hi[nt >> 1][(nt & 1) * 2];
                    mma_f16(acc[mt][nt], a_hi[mt], bh);
                    if (ALO) mma_f16(acc[mt][nt], a_lo[mt], bh);
                }
        }
        buf ^= 1;
    }

#pragma unroll
    for (int mt = 0; mt < 2; mt++) {
        const int r = row0 + warpM * 32 + mt * 16 + (lane >> 2);
#pragma unroll
        for (int nt = 0; nt < 8; nt++) {
            const int col = col0 + warpN * 64 + nt * 8 + (lane & 3) * 2;
            const float b0 = bias[col], b1 = bias[col + 1];
            const float o0 = acc[mt][nt][0] + b0, o1 = acc[mt][nt][1] + b1;
            const float o2 = acc[mt][nt][2] + b0, o3 = acc[mt][nt][3] + b1;
            if (SPLIT) {
                *(uint32_t*)&Chi[(size_t)r * DMODEL + col]       = pack_h2(o0, o1);
                *(uint32_t*)&Chi[(size_t)(r + 8) * DMODEL + col] = pack_h2(o2, o3);
            } else {
                *(float2*)&Cf[(size_t)r * DMODEL + col]       = make_float2(o0, o1);
                *(float2*)&Cf[(size_t)(r + 8) * DMODEL + col] = make_float2(o2, o3);
            }
        }
    }
}

__global__ void __launch_bounds__(256) qkv_mma(
    const float* __restrict__ bq, const float* __restrict__ bk, const float* __restrict__ bv)
{
    const int z = blockIdx.z;
    const float* bias = (z == 0) ? bq : (z == 1) ? bk : bv;
    gemm_mma_core<true, false>(g_hiX + z * NX, nullptr, g_hiW + z * NW, bias,
                               nullptr, g_hiQKV + z * NX);
}

__global__ void __launch_bounds__(256) out_mma(
    const float* __restrict__ bo, float* __restrict__ C)
{
    gemm_mma_core<false, true>(g_hiC, g_loC, g_hiW + 3 * NW, bo, C, nullptr);
}

// ---------------------------------------------------------------------------
// Fused flash attention with fp16 expS fragment cache.
// Pass 1: QK^T -> exp -> rowsums; store expS fragments (fp16, reg layout) to
//         g_expS scratch (coalesced).
// Pass 2: reload fragments, scale by rowinv (fp16), write fp32 attn once,
//         PV MMA. No QK recompute, no exp in pass 2.
// Smem: Q 16K | K 8K (pass1); V 8K @0 (pass2); red 32K (epilogue); rsum @32K
// ---------------------------------------------------------------------------
#define ATT_SMEM (32768 + 512)

__global__ void __launch_bounds__(256) attn_fused(float* __restrict__ attn)
{
    extern __shared__ char sm[];
    const uint32_t sQh = smem_u32(sm);
    const uint32_t sKh = sQh + 16384;
    const uint32_t sVh = sQh;          // pass 2 reuses Q region for V
    float* rsum = (float*)(sm + 32768);

    const int tid = threadIdx.x, lane = tid & 31, wid = tid >> 5;
    const int warpM = wid & 3, warpN = wid >> 2;
    const int p = blockIdx.y, bb = p >> 4, h = p & 15;
    const int row0 = blockIdx.x * 128;
    uint32_t* const scratch = (uint32_t*)g_expS +
        ((size_t)(p * 16 + blockIdx.x) * 32) * 4096 + (size_t)tid * 16;

#pragma unroll
    for (int ps = 0; ps < 4; ps++) {
        const int u = tid + ps * 256;
        const int row = u >> 3, ch = u & 7;
        const size_t ge = (size_t)(bb * S_LEN + row0 + row) * DMODEL + h * HDIM + ch * 8;
        *(uint4*)(sm + SWB128(row, ch)) = *(const uint4*)(g_hiQKV + ge);
    }
    if (tid < 128) rsum[tid] = 0.f;

    const int arowl = warpM * 32 + (lane & 7) + ((lane >> 3) & 1) * 8;
    const int achl  = (lane >> 4) & 1;
    const int browl = warpN * 32 + (lane & 7) + ((lane >> 4) & 1) * 8;
    const int bchl  = (lane >> 3) & 1;
    const int vrowl = (lane & 7) + ((lane >> 3) & 1) * 8;
    const int vtog  = (lane >> 4) & 1;
    const float sc = 0.125f;

    // ---------------- pass 1: QK^T -> exp -> rowsums + scratch ----------------
    float rs[4] = {0.f, 0.f, 0.f, 0.f};
    for (int c = 0; c < 32; c++) {
        const int c0 = c * 64;
        __syncthreads();
#pragma unroll
        for (int ps = 0; ps < 2; ps++) {
            const int u = tid + ps * 256;
            const int row = u >> 3, ch = u & 7;
            const size_t ge = NX + (size_t)(bb * S_LEN + c0 + row) * DMODEL + h * HDIM + ch * 8;
            *(uint4*)(sm + 16384 + SWB128(row, ch)) = *(const uint4*)(g_hiQKV + ge);
        }
        __syncthreads();

        float acc[2][4][4];
#pragma unroll
        for (int mt = 0; mt < 2; mt++)
#pragma unroll
            for (int nt = 0; nt < 4; nt++)
#pragma unroll
                for (int e = 0; e < 4; e++) acc[mt][nt][e] = 0.f;
#pragma unroll
        for (int ks = 0; ks < 4; ks++) {
            uint32_t a_hi[2][4], b_hi[2][4];
#pragma unroll
            for (int mt = 0; mt < 2; mt++)
                ldsm4(a_hi[mt], sQh + SWB128(arowl + mt * 16, ks * 2 + achl));
#pragma unroll
            for (int np = 0; np < 2; np++)
                ldsm4(b_hi[np], sKh + SWB128(browl + np * 16, ks * 2 + bchl));
#pragma unroll
            for (int mt = 0; mt < 2; mt++)
#pragma unroll
                for (int nt = 0; nt < 4; nt++)
                    mma_f16(acc[mt][nt], a_hi[mt], &b_hi[nt >> 1][(nt & 1) * 2]);
        }

        uint32_t frag[16];
#pragma unroll
        for (int mt = 0; mt < 2; mt++)
#pragma unroll
            for (int nt = 0; nt < 4; nt++) {
                const float e0 = __expf(acc[mt][nt][0] * sc);
                const float e1 = __expf(acc[mt][nt][1] * sc);
                const float e2 = __expf(acc[mt][nt][2] * sc);
                const float e3 = __expf(acc[mt][nt][3] * sc);
                rs[mt * 2 + 0] += e0 + e1;
                rs[mt * 2 + 1] += e2 + e3;
                frag[(mt * 4 + nt) * 2 + 0] = pack_h2(e0, e1);
                frag[(mt * 4 + nt) * 2 + 1] = pack_h2(e2, e3);
            }
        uint32_t* sp = scratch + (size_t)c * 4096;
#pragma unroll
        for (int j = 0; j < 4; j++)
            *(uint4*)(sp + j * 4) = *(uint4*)(frag + j * 4);
    }
#pragma unroll
    for (int i = 0; i < 4; i++) {
        rs[i] += __shfl_xor_sync(0xffffffffu, rs[i], 1);
        rs[i] += __shfl_xor_sync(0xffffffffu, rs[i], 2);
    }
    if ((lane & 3) == 0) {
#pragma unroll
        for (int mt = 0; mt < 2; mt++) {
            atomicAdd(&rsum[warpM * 32 + mt * 16 + (lane >> 2)],     rs[mt * 2 + 0]);
            atomicAdd(&rsum[warpM * 32 + mt * 16 + (lane >> 2) + 8], rs[mt * 2 + 1]);
        }
    }
    __syncthreads();
    if (tid < 128) rsum[tid] = 1.0f / rsum[tid];
    __syncthreads();
    __half2 rinv2[2][2];
#pragma unroll
    for (int mt = 0; mt < 2; mt++) {
        rinv2[mt][0] = __float2half2_rn(rsum[warpM * 32 + mt * 16 + (lane >> 2)]);
        rinv2[mt][1] = __float2half2_rn(rsum[warpM * 32 + mt * 16 + (lane >> 2) + 8]);
    }

    // ---------------- pass 2: reload expS, scale, write attn, PV ----------------
    float ctx[2][8][4];
#pragma unroll
    for (int mt = 0; mt < 2; mt++)
#pragma unroll
        for (int nt = 0; nt < 8; nt++)
#pragma unroll
            for (int e = 0; e < 4; e++) ctx[mt][nt][e] = 0.f;

    for (int c = 0; c < 32; c++) {
        const int c0 = c * 64;
        __syncthreads();
#pragma unroll
        for (int ps = 0; ps < 2; ps++) {
            const int u = tid + ps * 256;
            const int row = u >> 3, ch = u & 7;
            const size_t geV = 2 * NX + (size_t)(bb * S_LEN + c0 + row) * DMODEL + h * HDIM + ch * 8;
            *(uint4*)(sm + SWB128(row, ch)) = *(const uint4*)(g_hiQKV + geV);
        }
        __syncthreads();

        uint32_t frag[16];
        uint32_t* sp = scratch + (size_t)c * 4096;
#pragma unroll
        for (int j = 0; j < 4; j++)
            *(uint4*)(frag + j * 4) = *(const uint4*)(sp + j * 4);

        // scale by rowinv (fp16) and write final attn
#pragma unroll
        for (int mt = 0; mt < 2; mt++) {
            const int r = row0 + warpM * 32 + mt * 16 + (lane >> 2);
#pragma unroll
            for (int nt = 0; nt < 4; nt++) {
                __half2 s0 = __hmul2(*(__half2*)&frag[(mt * 4 + nt) * 2 + 0], rinv2[mt][0]);
                __half2 s1 = __hmul2(*(__half2*)&frag[(mt * 4 + nt) * 2 + 1], rinv2[mt][1]);
                frag[(mt * 4 + nt) * 2 + 0] = *(uint32_t*)&s0;
                frag[(mt * 4 + nt) * 2 + 1] = *(uint32_t*)&s1;
                const int col = c0 + warpN * 32 + nt * 8 + (lane & 3) * 2;
                const size_t gi = ((size_t)(p * S_LEN) + r) * S_LEN + col;
                float2 f0 = __half22float2(s0);
                float2 f1 = __half22float2(s1);
                *(float2*)&attn[gi]             = f0;
                *(float2*)&attn[gi + 8 * S_LEN] = f1;
            }
        }

        // PV: this warp handles its 32 keys (2 groups of 16), full hd=64
#pragma unroll
        for (int kg = 0; kg < 2; kg++) {
            uint32_t ah[2][4];
#pragma unroll
            for (int mt = 0; mt < 2; mt++) {
                ah[mt][0] = frag[(mt * 4 + 2 * kg) * 2 + 0];
                ah[mt][1] = frag[(mt * 4 + 2 * kg) * 2 + 1];
                ah[mt][2] = frag[(mt * 4 + 2 * kg + 1) * 2 + 0];
                ah[mt][3] = frag[(mt * 4 + 2 * kg + 1) * 2 + 1];
            }
            uint32_t bh[4][4];
            const int kb = warpN * 32 + kg * 16;
#pragma unroll
            for (int ld = 0; ld < 4; ld++)
                ldsm4t(bh[ld], sVh + SWB128(kb + vrowl, ld * 2 + vtog));
#pragma unroll
            for (int mt = 0; mt < 2; mt++)
#pragma unroll
                for (int nt = 0; nt < 8; nt++)
                    mma_f16(ctx[mt][nt], ah[mt], &bh[nt >> 1][(nt & 1) * 2]);
        }
    }

    // cross-warpN ctx reduction via smem
    __syncthreads();
    float* red = (float*)sm;
    if (warpN == 1) {
#pragma unroll
        for (int mt = 0; mt < 2; mt++) {
            const int rl = warpM * 32 + mt * 16 + (lane >> 2);
#pragma unroll
            for (int nt = 0; nt < 8; nt++) {
                const int col = nt * 8 + (lane & 3) * 2;
                *(float2*)&red[rl * 64 + col]       = make_float2(ctx[mt][nt][0], ctx[mt][nt][1]);
                *(float2*)&red[(rl + 8) * 64 + col] = make_float2(ctx[mt][nt][2], ctx[mt][nt][3]);
            }
        }
    }
    __syncthreads();
    if (warpN == 0) {
#pragma unroll
        for (int mt = 0; mt < 2; mt++) {
            const int rl = warpM * 32 + mt * 16 + (lane >> 2);
            const size_t gr0 = (size_t)(bb * S_LEN + row0 + rl) * DMODEL + h * HDIM;
            const size_t gr1 = gr0 + (size_t)8 * DMODEL;
#pragma unroll
            for (int nt = 0; nt < 8; nt++) {
                const int col = nt * 8 + (lane & 3) * 2;
                float2 s0 = *(float2*)&red[rl * 64 + col];
                float2 s1 = *(float2*)&red[(rl + 8) * 64 + col];
                const float o0 = ctx[mt][nt][0] + s0.x, o1 = ctx[mt][nt][1] + s0.y;
                const float o2 = ctx[mt][nt][2] + s1.x, o3 = ctx[mt][nt][3] + s1.y;
                uint32_t h01, l01, h23, l23;
                split_pair(o0, o1, h01, l01);
                split_pair(o2, o3, h23, l23);
                *(uint32_t*)&g_hiC[gr0 + col] = h01;
                *(uint32_t*)&g_loC[gr0 + col] = l01;
                *(uint32_t*)&g_hiC[gr1 + col] = h23;
                *(uint32_t*)&g_loC[gr1 + col] = l23;
            }
        }
    }
}

// ---------------------------------------------------------------------------
extern "C" void kernel_launch(void* const* d_in, const int* in_sizes, int n_in,
                              void* d_out, int out_size) {
    const float* query = (const float*)d_in[0];
    const float* key_  = (const float*)d_in[1];
    const float* value = (const float*)d_in[2];
    const float* Wq = (const float*)d_in[3];
    const float* bq = (const float*)d_in[4];
    const float* Wk = (const float*)d_in[5];
    const float* bk = (const float*)d_in[6];
    const float* Wv = (const float*)d_in[7];
    const float* bv = (const float*)d_in[8];
    const float* Wo = (const float*)d_in[9];
    const float* bo = (const float*)d_in[10];

    float* outp = (float*)d_out;
    float* attn = outp + NX;          // tuple output: (out, attn)

    static int attr_set = 0;
    if (!attr_set) {
        cudaFuncSetAttribute(attn_fused, cudaFuncAttributeMaxDynamicSharedMemorySize, ATT_SMEM);
        attr_set = 1;
    }

    ConvSrcs cs;
    cs.s[0] = query; cs.s[1] = key_; cs.s[2] = value;
    cs.s[3] = Wq; cs.s[4] = Wk; cs.s[5] = Wv; cs.s[6] = Wo;
    conv_all<<<16384, 256>>>(cs);

    qkv_mma<<<dim3(DMODEL / 128, MROWS / 128, 3), 256>>>(bq, bk, bv);
    attn_fused<<<dim3(S_LEN / 128, NPAIRS), 256, ATT_SMEM>>>(attn);
    out_mma<<<dim3(DMODEL / 128, MROWS / 128), 256>>>(bo, outp);
}

// round 13
// speedup vs baseline: 1.7470x; 1.0818x over previous
#include <cuda_runtime.h>
#include <cuda_fp16.h>
#include <cstdint>

#define S_LEN  2048
#define DMODEL 1024
#define NHEAD  16
#define HDIM   64
#define MROWS  4096   // S*B
#define NPAIRS 32     // B*NHEAD
#define NX     ((size_t)MROWS * DMODEL)
#define NW     ((size_t)DMODEL * DMODEL)

// ---------------- scratch globals (allocation-free rule) ----------------
__device__ __half g_hiX[(size_t)3 * NX];    // converted q/k/v inputs (fp16 hi)
__device__ __half g_hiW[(size_t)4 * NW];    // converted Wq,Wk,Wv,Wo (hi)
__device__ __half g_hiQKV[(size_t)3 * NX];  // projected Q,K,V (fp16)
__device__ __half g_hiC[NX];                // attention context (fp16)
__device__ __half g_expS[(size_t)NPAIRS * S_LEN * S_LEN];  // unnorm expS frags

// ---------------- helpers ----------------
__device__ __forceinline__ uint32_t smem_u32(const void* p) {
    uint32_t a;
    asm("{ .reg .u64 t; cvta.to.shared.u64 t, %1; cvt.u32.u64 %0, t; }" : "=r"(a) : "l"(p));
    return a;
}
__device__ __forceinline__ void ldsm4(uint32_t* r, uint32_t a) {
    asm volatile("ldmatrix.sync.aligned.m8n8.x4.shared.b16 {%0,%1,%2,%3}, [%4];"
        : "=r"(r[0]), "=r"(r[1]), "=r"(r[2]), "=r"(r[3]) : "r"(a));
}
__device__ __forceinline__ void ldsm4t(uint32_t* r, uint32_t a) {
    asm volatile("ldmatrix.sync.aligned.m8n8.x4.trans.shared.b16 {%0,%1,%2,%3}, [%4];"
        : "=r"(r[0]), "=r"(r[1]), "=r"(r[2]), "=r"(r[3]) : "r"(a));
}
__device__ __forceinline__ void mma_f16(float* d, const uint32_t* a, const uint32_t* b) {
    asm volatile("mma.sync.aligned.m16n8k16.row.col.f32.f16.f16.f32 "
        "{%0,%1,%2,%3},{%4,%5,%6,%7},{%8,%9},{%0,%1,%2,%3};"
        : "+f"(d[0]), "+f"(d[1]), "+f"(d[2]), "+f"(d[3])
        : "r"(a[0]), "r"(a[1]), "r"(a[2]), "r"(a[3]), "r"(b[0]), "r"(b[1]));
}
// 64B-row swizzle (GEMM tiles)
#define SWB(row, ch) (((row) << 6) + ((((ch) ^ (((row) >> 1) & 3))) << 4))
// 128B-row swizzle (attention tiles)
#define SWB128(row, ch) (((row) << 7) + ((((ch) ^ ((row) & 7))) << 4))

__device__ __forceinline__ uint32_t pack_h2(float a, float b) {
    __half2 h = __floats2half2_rn(a, b);
    return *(uint32_t*)&h;
}

// ---------------- batched fp32 -> fp16 (hi) conversion ----------------
struct ConvSrcs { const float* s[7]; };

__global__ void __launch_bounds__(256) conv_all(ConvSrcs p)
{
    const int b = blockIdx.x;
    int t; size_t eb;
    __half* dst;
    if (b < 12288) {
        t = b >> 12;
        eb = (size_t)(b & 4095) * 1024;
        dst = g_hiX + (size_t)t * NX;
    } else {
        const int w = b - 12288;
        t = 3 + (w >> 10);
        eb = (size_t)(w & 1023) * 1024;
        dst = g_hiW + (size_t)(t - 3) * NW;
    }
    const size_t i = eb + (size_t)threadIdx.x * 4;
    float4 v = *(const float4*)(p.s[t] + i);
    *(uint2*)(dst + i) = make_uint2(pack_h2(v.x, v.y), pack_h2(v.z, v.w));
}

// ---------------------------------------------------------------------------
// mma.sync fp16 1-term GEMM: C[128 x 128 per block] = Ah * Wh^T + bias
// 256 threads = 8 warps (4 m-warps x 2 n-warps), warp tile 32x64.
// ---------------------------------------------------------------------------
template <bool SPLIT>
__device__ __forceinline__ void gemm_mma_core(
    const __half* __restrict__ Ahi, const __half* __restrict__ Whi,
    const float* __restrict__ bias, float* __restrict__ Cf,
    __half* __restrict__ Chi)
{
    constexpr int W_OFF = 8192;
    constexpr int BUFSZ = 16384;
    __shared__ char smbuf[2 * BUFSZ];
    const int tid = threadIdx.x, lane = tid & 31, wid = tid >> 5;
    const int warpM = wid & 3, warpN = wid >> 2;
    const int row0 = blockIdx.y * 128, col0 = blockIdx.x * 128;
    const uint32_t sb = smem_u32(smbuf);

    const int grow = tid >> 2, gch = tid & 3;
    const size_t aoff0 = (size_t)(row0 + grow) * (DMODEL * 2) + gch * 16;
    const size_t aoff1 = aoff0 + (size_t)64 * (DMODEL * 2);
    const size_t woff0 = (size_t)(col0 + grow) * (DMODEL * 2) + gch * 16;
    const size_t woff1 = woff0 + (size_t)64 * (DMODEL * 2);
    const uint32_t d0 = SWB(grow, gch);
    const uint32_t d1 = SWB(grow + 64, gch);

    float acc[2][8][4];
#pragma unroll
    for (int mt = 0; mt < 2; mt++)
#pragma unroll
        for (int nt = 0; nt < 8; nt++)
#pragma unroll
            for (int e = 0; e < 4; e++) acc[mt][nt][e] = 0.f;

    uint4 pre[4];
    pre[0] = *(const uint4*)((const char*)Ahi + aoff0);
    pre[1] = *(const uint4*)((const char*)Ahi + aoff1);
    pre[2] = *(const uint4*)((const char*)Whi + woff0);
    pre[3] = *(const uint4*)((const char*)Whi + woff1);

    const int arowl = warpM * 32 + (lane & 7) + ((lane >> 3) & 1) * 8;
    const int achl  = (lane >> 4) & 1;
    const int brow8 = (lane & 7) + ((lane >> 4) & 1) * 8;
    const int bchl  = (lane >> 3) & 1;

    int buf = 0;
    for (int c = 0; c < 32; c++) {
        char* base = smbuf + buf * BUFSZ;
        *(uint4*)(base + 0     + d0) = pre[0];
        *(uint4*)(base + 0     + d1) = pre[1];
        *(uint4*)(base + W_OFF + d0) = pre[2];
        *(uint4*)(base + W_OFF + d1) = pre[3];
        __syncthreads();

        if (c + 1 < 32) {
            const size_t cb = (size_t)(c + 1) * 64;
            pre[0] = *(const uint4*)((const char*)Ahi + aoff0 + cb);
            pre[1] = *(const uint4*)((const char*)Ahi + aoff1 + cb);
            pre[2] = *(const uint4*)((const char*)Whi + woff0 + cb);
            pre[3] = *(const uint4*)((const char*)Whi + woff1 + cb);
        }

        const uint32_t bb = sb + buf * BUFSZ;
#pragma unroll
        for (int ks = 0; ks < 2; ks++) {
            uint32_t a_hi[2][4], b_hi[4][4];
#pragma unroll
            for (int mt = 0; mt < 2; mt++)
                ldsm4(a_hi[mt], bb + SWB(arowl + mt * 16, ks * 2 + achl));
#pragma unroll
            for (int np = 0; np < 4; np++)
                ldsm4(b_hi[np], bb + W_OFF + SWB(warpN * 64 + np * 16 + brow8, ks * 2 + bchl));
#pragma unroll
            for (int mt = 0; mt < 2; mt++)
#pragma unroll
                for (int nt = 0; nt < 8; nt++)
                    mma_f16(acc[mt][nt], a_hi[mt], &b_hi[nt >> 1][(nt & 1) * 2]);
        }
        buf ^= 1;
    }

#pragma unroll
    for (int mt = 0; mt < 2; mt++) {
        const int r = row0 + warpM * 32 + mt * 16 + (lane >> 2);
#pragma unroll
        for (int nt = 0; nt < 8; nt++) {
            const int col = col0 + warpN * 64 + nt * 8 + (lane & 3) * 2;
            const float b0 = bias[col], b1 = bias[col + 1];
            const float o0 = acc[mt][nt][0] + b0, o1 = acc[mt][nt][1] + b1;
            const float o2 = acc[mt][nt][2] + b0, o3 = acc[mt][nt][3] + b1;
            if (SPLIT) {
                *(uint32_t*)&Chi[(size_t)r * DMODEL + col]       = pack_h2(o0, o1);
                *(uint32_t*)&Chi[(size_t)(r + 8) * DMODEL + col] = pack_h2(o2, o3);
            } else {
                *(float2*)&Cf[(size_t)r * DMODEL + col]       = make_float2(o0, o1);
                *(float2*)&Cf[(size_t)(r + 8) * DMODEL + col] = make_float2(o2, o3);
            }
        }
    }
}

__global__ void __launch_bounds__(256) qkv_mma(
    const float* __restrict__ bq, const float* __restrict__ bk, const float* __restrict__ bv)
{
    const int z = blockIdx.z;
    const float* bias = (z == 0) ? bq : (z == 1) ? bk : bv;
    gemm_mma_core<true>(g_hiX + z * NX, g_hiW + z * NW, bias, nullptr, g_hiQKV + z * NX);
}

__global__ void __launch_bounds__(256) out_mma(
    const float* __restrict__ bo, float* __restrict__ C)
{
    gemm_mma_core<false>(g_hiC, g_hiW + 3 * NW, bo, C, nullptr);
}

// ---------------------------------------------------------------------------
// Fused flash attention with fp16 expS fragment cache.
// Pass 1: QK^T -> exp -> rowsums; store expS fragments to g_expS (coalesced).
// Pass 2: prefetch fragments (before V staging), scale by rowinv, write fp32
//         attn once, PV MMA. Ctx written fp16 (hi only).
// ---------------------------------------------------------------------------
#define ATT_SMEM (32768 + 512)

__global__ void __launch_bounds__(256) attn_fused(float* __restrict__ attn)
{
    extern __shared__ char sm[];
    const uint32_t sQh = smem_u32(sm);
    const uint32_t sKh = sQh + 16384;
    const uint32_t sVh = sQh;          // pass 2 reuses Q region for V
    float* rsum = (float*)(sm + 32768);

    const int tid = threadIdx.x, lane = tid & 31, wid = tid >> 5;
    const int warpM = wid & 3, warpN = wid >> 2;
    const int p = blockIdx.y, bb = p >> 4, h = p & 15;
    const int row0 = blockIdx.x * 128;
    uint32_t* const scratch = (uint32_t*)g_expS +
        ((size_t)(p * 16 + blockIdx.x) * 32) * 4096 + (size_t)tid * 16;

#pragma unroll
    for (int ps = 0; ps < 4; ps++) {
        const int u = tid + ps * 256;
        const int row = u >> 3, ch = u & 7;
        const size_t ge = (size_t)(bb * S_LEN + row0 + row) * DMODEL + h * HDIM + ch * 8;
        *(uint4*)(sm + SWB128(row, ch)) = *(const uint4*)(g_hiQKV + ge);
    }
    if (tid < 128) rsum[tid] = 0.f;

    const int arowl = warpM * 32 + (lane & 7) + ((lane >> 3) & 1) * 8;
    const int achl  = (lane >> 4) & 1;
    const int browl = warpN * 32 + (lane & 7) + ((lane >> 4) & 1) * 8;
    const int bchl  = (lane >> 3) & 1;
    const int vrowl = (lane & 7) + ((lane >> 3) & 1) * 8;
    const int vtog  = (lane >> 4) & 1;
    const float sc = 0.125f;

    // ---------------- pass 1: QK^T -> exp -> rowsums + scratch ----------------
    float rs[4] = {0.f, 0.f, 0.f, 0.f};
    for (int c = 0; c < 32; c++) {
        const int c0 = c * 64;
        __syncthreads();
#pragma unroll
        for (int ps = 0; ps < 2; ps++) {
            const int u = tid + ps * 256;
            const int row = u >> 3, ch = u & 7;
            const size_t ge = NX + (size_t)(bb * S_LEN + c0 + row) * DMODEL + h * HDIM + ch * 8;
            *(uint4*)(sm + 16384 + SWB128(row, ch)) = *(const uint4*)(g_hiQKV + ge);
        }
        __syncthreads();

        float acc[2][4][4];
#pragma unroll
        for (int mt = 0; mt < 2; mt++)
#pragma unroll
            for (int nt = 0; nt < 4; nt++)
#pragma unroll
                for (int e = 0; e < 4; e++) acc[mt][nt][e] = 0.f;
#pragma unroll
        for (int ks = 0; ks < 4; ks++) {
            uint32_t a_hi[2][4], b_hi[2][4];
#pragma unroll
            for (int mt = 0; mt < 2; mt++)
                ldsm4(a_hi[mt], sQh + SWB128(arowl + mt * 16, ks * 2 + achl));
#pragma unroll
            for (int np = 0; np < 2; np++)
                ldsm4(b_hi[np], sKh + SWB128(browl + np * 16, ks * 2 + bchl));
#pragma unroll
            for (int mt = 0; mt < 2; mt++)
#pragma unroll
                for (int nt = 0; nt < 4; nt++)
                    mma_f16(acc[mt][nt], a_hi[mt], &b_hi[nt >> 1][(nt & 1) * 2]);
        }

        uint32_t frag[16];
#pragma unroll
        for (int mt = 0; mt < 2; mt++)
#pragma unroll
            for (int nt = 0; nt < 4; nt++) {
                const float e0 = __expf(acc[mt][nt][0] * sc);
                const float e1 = __expf(acc[mt][nt][1] * sc);
                const float e2 = __expf(acc[mt][nt][2] * sc);
                const float e3 = __expf(acc[mt][nt][3] * sc);
                rs[mt * 2 + 0] += e0 + e1;
                rs[mt * 2 + 1] += e2 + e3;
                frag[(mt * 4 + nt) * 2 + 0] = pack_h2(e0, e1);
                frag[(mt * 4 + nt) * 2 + 1] = pack_h2(e2, e3);
            }
        uint32_t* sp = scratch + (size_t)c * 4096;
#pragma unroll
        for (int j = 0; j < 4; j++)
            *(uint4*)(sp + j * 4) = *(uint4*)(frag + j * 4);
    }
#pragma unroll
    for (int i = 0; i < 4; i++) {
        rs[i] += __shfl_xor_sync(0xffffffffu, rs[i], 1);
        rs[i] += __shfl_xor_sync(0xffffffffu, rs[i], 2);
    }
    if ((lane & 3) == 0) {
#pragma unroll
        for (int mt = 0; mt < 2; mt++) {
            atomicAdd(&rsum[warpM * 32 + mt * 16 + (lane >> 2)],     rs[mt * 2 + 0]);
            atomicAdd(&rsum[warpM * 32 + mt * 16 + (lane >> 2) + 8], rs[mt * 2 + 1]);
        }
    }
    __syncthreads();
    if (tid < 128) rsum[tid] = 1.0f / rsum[tid];
    __syncthreads();
    __half2 rinv2[2][2];
#pragma unroll
    for (int mt = 0; mt < 2; mt++) {
        rinv2[mt][0] = __float2half2_rn(rsum[warpM * 32 + mt * 16 + (lane >> 2)]);
        rinv2[mt][1] = __float2half2_rn(rsum[warpM * 32 + mt * 16 + (lane >> 2) + 8]);
    }

    // ---------------- pass 2: prefetch expS, scale, write attn, PV ----------------
    float ctx[2][8][4];
#pragma unroll
    for (int mt = 0; mt < 2; mt++)
#pragma unroll
        for (int nt = 0; nt < 8; nt++)
#pragma unroll
            for (int e = 0; e < 4; e++) ctx[mt][nt][e] = 0.f;

    for (int c = 0; c < 32; c++) {
        const int c0 = c * 64;

        // prefetch expS fragments FIRST (independent of smem) so the LDG
        // latency overlaps the V staging + syncs below
        uint32_t frag[16];
        uint32_t* sp = scratch + (size_t)c * 4096;
#pragma unroll
        for (int j = 0; j < 4; j++)
            *(uint4*)(frag + j * 4) = *(const uint4*)(sp + j * 4);

        __syncthreads();
#pragma unroll
        for (int ps = 0; ps < 2; ps++) {
            const int u = tid + ps * 256;
            const int row = u >> 3, ch = u & 7;
            const size_t geV = 2 * NX + (size_t)(bb * S_LEN + c0 + row) * DMODEL + h * HDIM + ch * 8;
            *(uint4*)(sm + SWB128(row, ch)) = *(const uint4*)(g_hiQKV + geV);
        }
        __syncthreads();

        // scale by rowinv (fp16) and write final attn
#pragma unroll
        for (int mt = 0; mt < 2; mt++) {
            const int r = row0 + warpM * 32 + mt * 16 + (lane >> 2);
#pragma unroll
            for (int nt = 0; nt < 4; nt++) {
                __half2 s0 = __hmul2(*(__half2*)&frag[(mt * 4 + nt) * 2 + 0], rinv2[mt][0]);
                __half2 s1 = __hmul2(*(__half2*)&frag[(mt * 4 + nt) * 2 + 1], rinv2[mt][1]);
                frag[(mt * 4 + nt) * 2 + 0] = *(uint32_t*)&s0;
                frag[(mt * 4 + nt) * 2 + 1] = *(uint32_t*)&s1;
                const int col = c0 + warpN * 32 + nt * 8 + (lane & 3) * 2;
                const size_t gi = ((size_t)(p * S_LEN) + r) * S_LEN + col;
                float2 f0 = __half22float2(s0);
                float2 f1 = __half22float2(s1);
                *(float2*)&attn[gi]             = f0;
                *(float2*)&attn[gi + 8 * S_LEN] = f1;
            }
        }

        // PV: this warp handles its 32 keys (2 groups of 16), full hd=64
#pragma unroll
        for (int kg = 0; kg < 2; kg++) {
            uint32_t ah[2][4];
#pragma unroll
            for (int mt = 0; mt < 2; mt++) {
                ah[mt][0] = frag[(mt * 4 + 2 * kg) * 2 + 0];
                ah[mt][1] = frag[(mt * 4 + 2 * kg) * 2 + 1];
                ah[mt][2] = frag[(mt * 4 + 2 * kg + 1) * 2 + 0];
                ah[mt][3] = frag[(mt * 4 + 2 * kg + 1) * 2 + 1];
            }
            uint32_t bh[4][4];
            const int kb = warpN * 32 + kg * 16;
#pragma unroll
            for (int ld = 0; ld < 4; ld++)
                ldsm4t(bh[ld], sVh + SWB128(kb + vrowl, ld * 2 + vtog));
#pragma unroll
            for (int mt = 0; mt < 2; mt++)
#pragma unroll
                for (int nt = 0; nt < 8; nt++)
                    mma_f16(ctx[mt][nt], ah[mt], &bh[nt >> 1][(nt & 1) * 2]);
        }
    }

    // cross-warpN ctx reduction via smem
    __syncthreads();
    float* red = (float*)sm;
    if (warpN == 1) {
#pragma unroll
        for (int mt = 0; mt < 2; mt++) {
            const int rl = warpM * 32 + mt * 16 + (lane >> 2);
#pragma unroll
            for (int nt = 0; nt < 8; nt++) {
                const int col = nt * 8 + (lane & 3) * 2;
                *(float2*)&red[rl * 64 + col]       = make_float2(ctx[mt][nt][0], ctx[mt][nt][1]);
                *(float2*)&red[(rl + 8) * 64 + col] = make_float2(ctx[mt][nt][2], ctx[mt][nt][3]);
            }
        }
    }
    __syncthreads();
    if (warpN == 0) {
#pragma unroll
        for (int mt = 0; mt < 2; mt++) {
            const int rl = warpM * 32 + mt * 16 + (lane >> 2);
            const size_t gr0 = (size_t)(bb * S_LEN + row0 + rl) * DMODEL + h * HDIM;
            const size_t gr1 = gr0 + (size_t)8 * DMODEL;
#pragma unroll
            for (int nt = 0; nt < 8; nt++) {
                const int col = nt * 8 + (lane & 3) * 2;
                float2 s0 = *(float2*)&red[rl * 64 + col];
                float2 s1 = *(float2*)&red[(rl + 8) * 64 + col];
                *(uint32_t*)&g_hiC[gr0 + col] = pack_h2(ctx[mt][nt][0] + s0.x, ctx[mt][nt][1] + s0.y);
                *(uint32_t*)&g_hiC[gr1 + col] = pack_h2(ctx[mt][nt][2] + s1.x, ctx[mt][nt][3] + s1.y);
            }
        }
    }
}

// ---------------------------------------------------------------------------
extern "C" void kernel_launch(void* const* d_in, const int* in_sizes, int n_in,
                              void* d_out, int out_size) {
    const float* query = (const float*)d_in[0];
    const float* key_  = (const float*)d_in[1];
    const float* value = (const float*)d_in[2];
    const float* Wq = (const float*)d_in[3];
    const float* bq = (const float*)d_in[4];
    const float* Wk = (const float*)d_in[5];
    const float* bk = (const float*)d_in[6];
    const float* Wv = (const float*)d_in[7];
    const float* bv = (const float*)d_in[8];
    const float* Wo = (const float*)d_in[9];
    const float* bo = (const float*)d_in[10];

    float* outp = (float*)d_out;
    float* attn = outp + NX;          // tuple output: (out, attn)

    static int attr_set = 0;
    if (!attr_set) {
        cudaFuncSetAttribute(attn_fused, cudaFuncAttributeMaxDynamicSharedMemorySize, ATT_SMEM);
        attr_set = 1;
    }

    ConvSrcs cs;
    cs.s[0] = query; cs.s[1] = key_; cs.s[2] = value;
    cs.s[3] = Wq; cs.s[4] = Wk; cs.s[5] = Wv; cs.s[6] = Wo;
    conv_all<<<16384, 256>>>(cs);

    qkv_mma<<<dim3(DMODEL / 128, MROWS / 128, 3), 256>>>(bq, bk, bv);
    attn_fused<<<dim3(S_LEN / 128, NPAIRS), 256, ATT_SMEM>>>(attn);
    out_mma<<<dim3(DMODEL / 128, MROWS / 128), 256>>>(bo, outp);
}

// round 14
// speedup vs baseline: 2.0112x; 1.1513x over previous
#include <cuda_runtime.h>
#include <cuda_fp16.h>
#include <cstdint>

#define S_LEN  2048
#define DMODEL 1024
#define NHEAD  16
#define HDIM   64
#define MROWS  4096   // S*B
#define NPAIRS 32     // B*NHEAD
#define NX     ((size_t)MROWS * DMODEL)
#define NW     ((size_t)DMODEL * DMODEL)

// ---------------- scratch globals (allocation-free rule) ----------------
__device__ __half g_hiX[(size_t)3 * NX];    // converted q/k/v inputs (fp16 hi)
__device__ __half g_hiW[(size_t)4 * NW];    // converted Wq,Wk,Wv,Wo (hi)
__device__ __half g_hiQKV[(size_t)3 * NX];  // projected Q,K,V (fp16)
__device__ __half g_hiC[NX];                // attention context (fp16)
__device__ __half g_expS[(size_t)NPAIRS * S_LEN * S_LEN];  // unnorm expS frags

// ---------------- helpers ----------------
__device__ __forceinline__ uint32_t smem_u32(const void* p) {
    uint32_t a;
    asm("{ .reg .u64 t; cvta.to.shared.u64 t, %1; cvt.u32.u64 %0, t; }" : "=r"(a) : "l"(p));
    return a;
}
__device__ __forceinline__ void ldsm4(uint32_t* r, uint32_t a) {
    asm volatile("ldmatrix.sync.aligned.m8n8.x4.shared.b16 {%0,%1,%2,%3}, [%4];"
        : "=r"(r[0]), "=r"(r[1]), "=r"(r[2]), "=r"(r[3]) : "r"(a));
}
__device__ __forceinline__ void ldsm4t(uint32_t* r, uint32_t a) {
    asm volatile("ldmatrix.sync.aligned.m8n8.x4.trans.shared.b16 {%0,%1,%2,%3}, [%4];"
        : "=r"(r[0]), "=r"(r[1]), "=r"(r[2]), "=r"(r[3]) : "r"(a));
}
__device__ __forceinline__ void mma_f16(float* d, const uint32_t* a, const uint32_t* b) {
    asm volatile("mma.sync.aligned.m16n8k16.row.col.f32.f16.f16.f32 "
        "{%0,%1,%2,%3},{%4,%5,%6,%7},{%8,%9},{%0,%1,%2,%3};"
        : "+f"(d[0]), "+f"(d[1]), "+f"(d[2]), "+f"(d[3])
        : "r"(a[0]), "r"(a[1]), "r"(a[2]), "r"(a[3]), "r"(b[0]), "r"(b[1]));
}
// 64B-row swizzle (GEMM tiles)
#define SWB(row, ch) (((row) << 6) + ((((ch) ^ (((row) >> 1) & 3))) << 4))
// 128B-row swizzle (attention tiles)
#define SWB128(row, ch) (((row) << 7) + ((((ch) ^ ((row) & 7))) << 4))

__device__ __forceinline__ uint32_t pack_h2(float a, float b) {
    __half2 h = __floats2half2_rn(a, b);
    return *(uint32_t*)&h;
}

// ---------------- batched fp32 -> fp16 (hi) conversion ----------------
struct ConvSrcs { const float* s[7]; };

__global__ void __launch_bounds__(256) conv_all(ConvSrcs p)
{
    const int b = blockIdx.x;
    int t; size_t eb;
    __half* dst;
    if (b < 12288) {
        t = b >> 12;
        eb = (size_t)(b & 4095) * 1024;
        dst = g_hiX + (size_t)t * NX;
    } else {
        const int w = b - 12288;
        t = 3 + (w >> 10);
        eb = (size_t)(w & 1023) * 1024;
        dst = g_hiW + (size_t)(t - 3) * NW;
    }
    const size_t i = eb + (size_t)threadIdx.x * 4;
    float4 v = *(const float4*)(p.s[t] + i);
    *(uint2*)(dst + i) = make_uint2(pack_h2(v.x, v.y), pack_h2(v.z, v.w));
}

// ---------------------------------------------------------------------------
// mma.sync fp16 1-term GEMM: C[128 x 128 per block] = Ah * Wh^T + bias
// 256 threads = 8 warps (4 m-warps x 2 n-warps), warp tile 32x64.
// Inner B loop restructured (load-1-tile -> use) to keep regs < 128 for
// 2 blocks/SM.
// ---------------------------------------------------------------------------
template <bool SPLIT>
__device__ __forceinline__ void gemm_mma_core(
    const __half* __restrict__ Ahi, const __half* __restrict__ Whi,
    const float* __restrict__ bias, float* __restrict__ Cf,
    __half* __restrict__ Chi)
{
    constexpr int W_OFF = 8192;
    constexpr int BUFSZ = 16384;
    __shared__ char smbuf[2 * BUFSZ];
    const int tid = threadIdx.x, lane = tid & 31, wid = tid >> 5;
    const int warpM = wid & 3, warpN = wid >> 2;
    const int row0 = blockIdx.y * 128, col0 = blockIdx.x * 128;
    const uint32_t sb = smem_u32(smbuf);

    const int grow = tid >> 2, gch = tid & 3;
    const size_t aoff0 = (size_t)(row0 + grow) * (DMODEL * 2) + gch * 16;
    const size_t aoff1 = aoff0 + (size_t)64 * (DMODEL * 2);
    const size_t woff0 = (size_t)(col0 + grow) * (DMODEL * 2) + gch * 16;
    const size_t woff1 = woff0 + (size_t)64 * (DMODEL * 2);
    const uint32_t d0 = SWB(grow, gch);
    const uint32_t d1 = SWB(grow + 64, gch);

    float acc[2][8][4];
#pragma unroll
    for (int mt = 0; mt < 2; mt++)
#pragma unroll
        for (int nt = 0; nt < 8; nt++)
#pragma unroll
            for (int e = 0; e < 4; e++) acc[mt][nt][e] = 0.f;

    uint4 pre[4];
    pre[0] = *(const uint4*)((const char*)Ahi + aoff0);
    pre[1] = *(const uint4*)((const char*)Ahi + aoff1);
    pre[2] = *(const uint4*)((const char*)Whi + woff0);
    pre[3] = *(const uint4*)((const char*)Whi + woff1);

    const int arowl = warpM * 32 + (lane & 7) + ((lane >> 3) & 1) * 8;
    const int achl  = (lane >> 4) & 1;
    const int brow8 = (lane & 7) + ((lane >> 4) & 1) * 8;
    const int bchl  = (lane >> 3) & 1;

    int buf = 0;
    for (int c = 0; c < 32; c++) {
        char* base = smbuf + buf * BUFSZ;
        *(uint4*)(base + 0     + d0) = pre[0];
        *(uint4*)(base + 0     + d1) = pre[1];
        *(uint4*)(base + W_OFF + d0) = pre[2];
        *(uint4*)(base + W_OFF + d1) = pre[3];
        __syncthreads();

        if (c + 1 < 32) {
            const size_t cb = (size_t)(c + 1) * 64;
            pre[0] = *(const uint4*)((const char*)Ahi + aoff0 + cb);
            pre[1] = *(const uint4*)((const char*)Ahi + aoff1 + cb);
            pre[2] = *(const uint4*)((const char*)Whi + woff0 + cb);
            pre[3] = *(const uint4*)((const char*)Whi + woff1 + cb);
        }

        const uint32_t bb = sb + buf * BUFSZ;
#pragma unroll
        for (int ks = 0; ks < 2; ks++) {
            uint32_t a_hi[2][4];
#pragma unroll
            for (int mt = 0; mt < 2; mt++)
                ldsm4(a_hi[mt], bb + SWB(arowl + mt * 16, ks * 2 + achl));
#pragma unroll
            for (int np = 0; np < 4; np++) {
                uint32_t bh4[4];
                ldsm4(bh4, bb + W_OFF + SWB(warpN * 64 + np * 16 + brow8, ks * 2 + bchl));
#pragma unroll
                for (int mt = 0; mt < 2; mt++) {
                    mma_f16(acc[mt][np * 2 + 0], a_hi[mt], &bh4[0]);
                    mma_f16(acc[mt][np * 2 + 1], a_hi[mt], &bh4[2]);
                }
            }
        }
        buf ^= 1;
    }

#pragma unroll
    for (int mt = 0; mt < 2; mt++) {
        const int r = row0 + warpM * 32 + mt * 16 + (lane >> 2);
#pragma unroll
        for (int nt = 0; nt < 8; nt++) {
            const int col = col0 + warpN * 64 + nt * 8 + (lane & 3) * 2;
            const float b0 = bias[col], b1 = bias[col + 1];
            const float o0 = acc[mt][nt][0] + b0, o1 = acc[mt][nt][1] + b1;
            const float o2 = acc[mt][nt][2] + b0, o3 = acc[mt][nt][3] + b1;
            if (SPLIT) {
                *(uint32_t*)&Chi[(size_t)r * DMODEL + col]       = pack_h2(o0, o1);
                *(uint32_t*)&Chi[(size_t)(r + 8) * DMODEL + col] = pack_h2(o2, o3);
            } else {
                *(float2*)&Cf[(size_t)r * DMODEL + col]       = make_float2(o0, o1);
                *(float2*)&Cf[(size_t)(r + 8) * DMODEL + col] = make_float2(o2, o3);
            }
        }
    }
}

__global__ void __launch_bounds__(256, 2) qkv_mma(
    const float* __restrict__ bq, const float* __restrict__ bk, const float* __restrict__ bv)
{
    const int z = blockIdx.z;
    const float* bias = (z == 0) ? bq : (z == 1) ? bk : bv;
    gemm_mma_core<true>(g_hiX + z * NX, g_hiW + z * NW, bias, nullptr, g_hiQKV + z * NX);
}

__global__ void __launch_bounds__(256, 2) out_mma(
    const float* __restrict__ bo, float* __restrict__ C)
{
    gemm_mma_core<false>(g_hiC, g_hiW + 3 * NW, bo, C, nullptr);
}

// ---------------------------------------------------------------------------
// Fused flash attention with fp16 expS fragment cache + double-buffered K/V
// (one __syncthreads per chunk).
// Pass 1: QK^T -> exp -> rowsums; expS fragments -> g_expS (coalesced).
// Pass 2: prefetch fragments, scale by rowinv, write fp32 attn, PV MMA.
// Smem: pass1: Q 16K | Kbuf0 8K | Kbuf1 8K | rsum @32768
//       pass2: Vbuf0 8K @0 | Vbuf1 8K @8192 ; epilogue red 32K @0
// ---------------------------------------------------------------------------
#define ATT_SMEM (32768 + 512)

__global__ void __launch_bounds__(256, 2) attn_fused(float* __restrict__ attn)
{
    extern __shared__ char sm[];
    const uint32_t sQh = smem_u32(sm);
    float* rsum = (float*)(sm + 32768);

    const int tid = threadIdx.x, lane = tid & 31, wid = tid >> 5;
    const int warpM = wid & 3, warpN = wid >> 2;
    const int p = blockIdx.y, bb = p >> 4, h = p & 15;
    const int row0 = blockIdx.x * 128;
    uint32_t* const scratch = (uint32_t*)g_expS +
        ((size_t)(p * 16 + blockIdx.x) * 32) * 4096 + (size_t)tid * 16;

    // per-thread staging coords (2 passes of 256 threads over 128x64 tiles)
    const int srow0 = tid >> 3,        sch0 = tid & 7;          // ps=0
    const int srow1 = (tid + 256) >> 3, sch1 = (tid + 256) & 7; // ps=1
    const uint32_t sso0 = SWB128(srow0, sch0);
    const uint32_t sso1 = SWB128(srow1, sch1);

    // stage Q tile (128 x 64)
#pragma unroll
    for (int ps = 0; ps < 4; ps++) {
        const int u = tid + ps * 256;
        const int row = u >> 3, ch = u & 7;
        const size_t ge = (size_t)(bb * S_LEN + row0 + row) * DMODEL + h * HDIM + ch * 8;
        *(uint4*)(sm + SWB128(row, ch)) = *(const uint4*)(g_hiQKV + ge);
    }
    // stage K chunk 0 into Kbuf0
    {
        const size_t g0 = NX + (size_t)(bb * S_LEN + srow0) * DMODEL + h * HDIM + sch0 * 8;
        const size_t g1 = NX + (size_t)(bb * S_LEN + srow1) * DMODEL + h * HDIM + sch1 * 8;
        *(uint4*)(sm + 16384 + sso0) = *(const uint4*)(g_hiQKV + g0);
        *(uint4*)(sm + 16384 + sso1) = *(const uint4*)(g_hiQKV + g1);
    }
    if (tid < 128) rsum[tid] = 0.f;
    __syncthreads();

    const int arowl = warpM * 32 + (lane & 7) + ((lane >> 3) & 1) * 8;
    const int achl  = (lane >> 4) & 1;
    const int browl = warpN * 32 + (lane & 7) + ((lane >> 4) & 1) * 8;
    const int bchl  = (lane >> 3) & 1;
    const int vrowl = (lane & 7) + ((lane >> 3) & 1) * 8;
    const int vtog  = (lane >> 4) & 1;
    const float sc = 0.125f;

    // ---------------- pass 1: QK^T -> exp -> rowsums + scratch ----------------
    float rs[4] = {0.f, 0.f, 0.f, 0.f};
    for (int c = 0; c < 32; c++) {
        // prefetch K chunk c+1 and store into the other buffer (no conflict)
        if (c + 1 < 32) {
            const int c1 = (c + 1) * 64;
            const size_t g0 = NX + (size_t)(bb * S_LEN + c1 + srow0) * DMODEL + h * HDIM + sch0 * 8;
            const size_t g1 = NX + (size_t)(bb * S_LEN + c1 + srow1) * DMODEL + h * HDIM + sch1 * 8;
            uint4 k0 = *(const uint4*)(g_hiQKV + g0);
            uint4 k1 = *(const uint4*)(g_hiQKV + g1);
            char* kb = sm + 16384 + ((c + 1) & 1) * 8192;
            *(uint4*)(kb + sso0) = k0;
            *(uint4*)(kb + sso1) = k1;
        }
        const uint32_t kcur = sQh + 16384 + (c & 1) * 8192;

        float acc[2][4][4];
#pragma unroll
        for (int mt = 0; mt < 2; mt++)
#pragma unroll
            for (int nt = 0; nt < 4; nt++)
#pragma unroll
                for (int e = 0; e < 4; e++) acc[mt][nt][e] = 0.f;
#pragma unroll
        for (int ks = 0; ks < 4; ks++) {
            uint32_t a_hi[2][4];
#pragma unroll
            for (int mt = 0; mt < 2; mt++)
                ldsm4(a_hi[mt], sQh + SWB128(arowl + mt * 16, ks * 2 + achl));
#pragma unroll
            for (int np = 0; np < 2; np++) {
                uint32_t bh4[4];
                ldsm4(bh4, kcur + SWB128(browl + np * 16, ks * 2 + bchl));
#pragma unroll
                for (int mt = 0; mt < 2; mt++) {
                    mma_f16(acc[mt][np * 2 + 0], a_hi[mt], &bh4[0]);
                    mma_f16(acc[mt][np * 2 + 1], a_hi[mt], &bh4[2]);
                }
            }
        }

        uint32_t frag[16];
#pragma unroll
        for (int mt = 0; mt < 2; mt++)
#pragma unroll
            for (int nt = 0; nt < 4; nt++) {
                const float e0 = __expf(acc[mt][nt][0] * sc);
                const float e1 = __expf(acc[mt][nt][1] * sc);
                const float e2 = __expf(acc[mt][nt][2] * sc);
                const float e3 = __expf(acc[mt][nt][3] * sc);
                rs[mt * 2 + 0] += e0 + e1;
                rs[mt * 2 + 1] += e2 + e3;
                frag[(mt * 4 + nt) * 2 + 0] = pack_h2(e0, e1);
                frag[(mt * 4 + nt) * 2 + 1] = pack_h2(e2, e3);
            }
        uint32_t* sp = scratch + (size_t)c * 4096;
#pragma unroll
        for (int j = 0; j < 4; j++)
            *(uint4*)(sp + j * 4) = *(uint4*)(frag + j * 4);
        __syncthreads();
    }
#pragma unroll
    for (int i = 0; i < 4; i++) {
        rs[i] += __shfl_xor_sync(0xffffffffu, rs[i], 1);
        rs[i] += __shfl_xor_sync(0xffffffffu, rs[i], 2);
    }
    if ((lane & 3) == 0) {
#pragma unroll
        for (int mt = 0; mt < 2; mt++) {
            atomicAdd(&rsum[warpM * 32 + mt * 16 + (lane >> 2)],     rs[mt * 2 + 0]);
            atomicAdd(&rsum[warpM * 32 + mt * 16 + (lane >> 2) + 8], rs[mt * 2 + 1]);
        }
    }
    __syncthreads();
    if (tid < 128) rsum[tid] = 1.0f / rsum[tid];
    __syncthreads();
    __half2 rinv2[2][2];
#pragma unroll
    for (int mt = 0; mt < 2; mt++) {
        rinv2[mt][0] = __float2half2_rn(rsum[warpM * 32 + mt * 16 + (lane >> 2)]);
        rinv2[mt][1] = __float2half2_rn(rsum[warpM * 32 + mt * 16 + (lane >> 2) + 8]);
    }

    // ---------------- pass 2: prefetch expS, scale, write attn, PV ----------------
    float ctx[2][8][4];
#pragma unroll
    for (int mt = 0; mt < 2; mt++)
#pragma unroll
        for (int nt = 0; nt < 8; nt++)
#pragma unroll
            for (int e = 0; e < 4; e++) ctx[mt][nt][e] = 0.f;

    // stage V chunk 0 into Vbuf0
    {
        const size_t g0 = 2 * NX + (size_t)(bb * S_LEN + srow0) * DMODEL + h * HDIM + sch0 * 8;
        const size_t g1 = 2 * NX + (size_t)(bb * S_LEN + srow1) * DMODEL + h * HDIM + sch1 * 8;
        *(uint4*)(sm + sso0) = *(const uint4*)(g_hiQKV + g0);
        *(uint4*)(sm + sso1) = *(const uint4*)(g_hiQKV + g1);
    }
    __syncthreads();

    for (int c = 0; c < 32; c++) {
        const int c0 = c * 64;

        // prefetch expS fragments (gmem; overlaps everything below)
        uint32_t frag[16];
        uint32_t* sp = scratch + (size_t)c * 4096;
#pragma unroll
        for (int j = 0; j < 4; j++)
            *(uint4*)(frag + j * 4) = *(const uint4*)(sp + j * 4);

        // prefetch V chunk c+1 and store into the other buffer
        if (c + 1 < 32) {
            const int c1 = (c + 1) * 64;
            const size_t g0 = 2 * NX + (size_t)(bb * S_LEN + c1 + srow0) * DMODEL + h * HDIM + sch0 * 8;
            const size_t g1 = 2 * NX + (size_t)(bb * S_LEN + c1 + srow1) * DMODEL + h * HDIM + sch1 * 8;
            uint4 v0 = *(const uint4*)(g_hiQKV + g0);
            uint4 v1 = *(const uint4*)(g_hiQKV + g1);
            char* vb = sm + ((c + 1) & 1) * 8192;
            *(uint4*)(vb + sso0) = v0;
            *(uint4*)(vb + sso1) = v1;
        }

        // scale by rowinv (fp16) and write final attn
#pragma unroll
        for (int mt = 0; mt < 2; mt++) {
            const int r = row0 + warpM * 32 + mt * 16 + (lane >> 2);
#pragma unroll
            for (int nt = 0; nt < 4; nt++) {
                __half2 s0 = __hmul2(*(__half2*)&frag[(mt * 4 + nt) * 2 + 0], rinv2[mt][0]);
                __half2 s1 = __hmul2(*(__half2*)&frag[(mt * 4 + nt) * 2 + 1], rinv2[mt][1]);
                frag[(mt * 4 + nt) * 2 + 0] = *(uint32_t*)&s0;
                frag[(mt * 4 + nt) * 2 + 1] = *(uint32_t*)&s1;
                const int col = c0 + warpN * 32 + nt * 8 + (lane & 3) * 2;
                const size_t gi = ((size_t)(p * S_LEN) + r) * S_LEN + col;
                *(float2*)&attn[gi]             = __half22float2(s0);
                *(float2*)&attn[gi + 8 * S_LEN] = __half22float2(s1);
            }
        }

        // PV on current V buffer
        const uint32_t vcur = sQh + (c & 1) * 8192;
#pragma unroll
        for (int kg = 0; kg < 2; kg++) {
            uint32_t ah[2][4];
#pragma unroll
            for (int mt = 0; mt < 2; mt++) {
                ah[mt][0] = frag[(mt * 4 + 2 * kg) * 2 + 0];
                ah[mt][1] = frag[(mt * 4 + 2 * kg) * 2 + 1];
                ah[mt][2] = frag[(mt * 4 + 2 * kg + 1) * 2 + 0];
                ah[mt][3] = frag[(mt * 4 + 2 * kg + 1) * 2 + 1];
            }
            const int kb = warpN * 32 + kg * 16;
#pragma unroll
            for (int ld = 0; ld < 4; ld++) {
                uint32_t bh4[4];
                ldsm4t(bh4, vcur + SWB128(kb + vrowl, ld * 2 + vtog));
#pragma unroll
                for (int mt = 0; mt < 2; mt++) {
                    mma_f16(ctx[mt][ld * 2 + 0], ah[mt], &bh4[0]);
                    mma_f16(ctx[mt][ld * 2 + 1], ah[mt], &bh4[2]);
                }
            }
        }
        __syncthreads();
    }

    // cross-warpN ctx reduction via smem
    float* red = (float*)sm;
    if (warpN == 1) {
#pragma unroll
        for (int mt = 0; mt < 2; mt++) {
            const int rl = warpM * 32 + mt * 16 + (lane >> 2);
#pragma unroll
            for (int nt = 0; nt < 8; nt++) {
                const int col = nt * 8 + (lane & 3) * 2;
                *(float2*)&red[rl * 64 + col]       = make_float2(ctx[mt][nt][0], ctx[mt][nt][1]);
                *(float2*)&red[(rl + 8) * 64 + col] = make_float2(ctx[mt][nt][2], ctx[mt][nt][3]);
            }
        }
    }
    __syncthreads();
    if (warpN == 0) {
#pragma unroll
        for (int mt = 0; mt < 2; mt++) {
            const int rl = warpM * 32 + mt * 16 + (lane >> 2);
            const size_t gr0 = (size_t)(bb * S_LEN + row0 + rl) * DMODEL + h * HDIM;
            const size_t gr1 = gr0 + (size_t)8 * DMODEL;
#pragma unroll
            for (int nt = 0; nt < 8; nt++) {
                const int col = nt * 8 + (lane & 3) * 2;
                float2 s0 = *(float2*)&red[rl * 64 + col];
                float2 s1 = *(float2*)&red[(rl + 8) * 64 + col];
                *(uint32_t*)&g_hiC[gr0 + col] = pack_h2(ctx[mt][nt][0] + s0.x, ctx[mt][nt][1] + s0.y);
                *(uint32_t*)&g_hiC[gr1 + col] = pack_h2(ctx[mt][nt][2] + s1.x, ctx[mt][nt][3] + s1.y);
            }
        }
    }
}

// ---------------------------------------------------------------------------
extern "C" void kernel_launch(void* const* d_in, const int* in_sizes, int n_in,
                              void* d_out, int out_size) {
    const float* query = (const float*)d_in[0];
    const float* key_  = (const float*)d_in[1];
    const float* value = (const float*)d_in[2];
    const float* Wq = (const float*)d_in[3];
    const float* bq = (const float*)d_in[4];
    const float* Wk = (const float*)d_in[5];
    const float* bk = (const float*)d_in[6];
    const float* Wv = (const float*)d_in[7];
    const float* bv = (const float*)d_in[8];
    const float* Wo = (const float*)d_in[9];
    const float* bo = (const float*)d_in[10];

    float* outp = (float*)d_out;
    float* attn = outp + NX;          // tuple output: (out, attn)

    static int attr_set = 0;
    if (!attr_set) {
        cudaFuncSetAttribute(attn_fused, cudaFuncAttributeMaxDynamicSharedMemorySize, ATT_SMEM);
        attr_set = 1;
    }

    ConvSrcs cs;
    cs.s[0] = query; cs.s[1] = key_; cs.s[2] = value;
    cs.s[3] = Wq; cs.s[4] = Wk; cs.s[5] = Wv; cs.s[6] = Wo;
    conv_all<<<16384, 256>>>(cs);

    qkv_mma<<<dim3(DMODEL / 128, MROWS / 128, 3), 256>>>(bq, bk, bv);
    attn_fused<<<dim3(S_LEN / 128, NPAIRS), 256, ATT_SMEM>>>(attn);
    out_mma<<<dim3(DMODEL / 128, MROWS / 128), 256>>>(bo, outp);
}

// round 15
// speedup vs baseline: 2.1805x; 1.0842x over previous
#include <cuda_runtime.h>
#include <cuda_fp16.h>
#include <cstdint>

#define S_LEN  2048
#define DMODEL 1024
#define NHEAD  16
#define HDIM   64
#define MROWS  4096   // S*B
#define NPAIRS 32     // B*NHEAD
#define NX     ((size_t)MROWS * DMODEL)
#define NW     ((size_t)DMODEL * DMODEL)

// ---------------- scratch globals (allocation-free rule) ----------------
__device__ __half g_hiX[(size_t)3 * NX];    // converted q/k/v inputs (fp16 hi)
__device__ __half g_hiW[(size_t)4 * NW];    // converted Wq,Wk,Wv,Wo (hi)
__device__ __half g_hiQKV[(size_t)3 * NX];  // projected Q,K,V (fp16)
__device__ __half g_hiC[NX];                // attention context (fp16)
__device__ float  g_rowinv[NPAIRS * S_LEN];
__device__ __half g_expS[(size_t)NPAIRS * S_LEN * S_LEN];  // unnorm expS frags

// ---------------- helpers ----------------
__device__ __forceinline__ uint32_t smem_u32(const void* p) {
    uint32_t a;
    asm("{ .reg .u64 t; cvta.to.shared.u64 t, %1; cvt.u32.u64 %0, t; }" : "=r"(a) : "l"(p));
    return a;
}
__device__ __forceinline__ void ldsm4(uint32_t* r, uint32_t a) {
    asm volatile("ldmatrix.sync.aligned.m8n8.x4.shared.b16 {%0,%1,%2,%3}, [%4];"
        : "=r"(r[0]), "=r"(r[1]), "=r"(r[2]), "=r"(r[3]) : "r"(a));
}
__device__ __forceinline__ void ldsm4t(uint32_t* r, uint32_t a) {
    asm volatile("ldmatrix.sync.aligned.m8n8.x4.trans.shared.b16 {%0,%1,%2,%3}, [%4];"
        : "=r"(r[0]), "=r"(r[1]), "=r"(r[2]), "=r"(r[3]) : "r"(a));
}
__device__ __forceinline__ void mma_f16(float* d, const uint32_t* a, const uint32_t* b) {
    asm volatile("mma.sync.aligned.m16n8k16.row.col.f32.f16.f16.f32 "
        "{%0,%1,%2,%3},{%4,%5,%6,%7},{%8,%9},{%0,%1,%2,%3};"
        : "+f"(d[0]), "+f"(d[1]), "+f"(d[2]), "+f"(d[3])
        : "r"(a[0]), "r"(a[1]), "r"(a[2]), "r"(a[3]), "r"(b[0]), "r"(b[1]));
}
// 64B-row swizzle (GEMM tiles)
#define SWB(row, ch) (((row) << 6) + ((((ch) ^ (((row) >> 1) & 3))) << 4))
// 128B-row swizzle (attention tiles)
#define SWB128(row, ch) (((row) << 7) + ((((ch) ^ ((row) & 7))) << 4))

__device__ __forceinline__ uint32_t pack_h2(float a, float b) {
    __half2 h = __floats2half2_rn(a, b);
    return *(uint32_t*)&h;
}

// ---------------- batched fp32 -> fp16 (hi) conversion ----------------
struct ConvSrcs { const float* s[7]; };

__global__ void __launch_bounds__(256) conv_all(ConvSrcs p)
{
    const int b = blockIdx.x;
    int t; size_t eb;
    __half* dst;
    if (b < 12288) {
        t = b >> 12;
        eb = (size_t)(b & 4095) * 1024;
        dst = g_hiX + (size_t)t * NX;
    } else {
        const int w = b - 12288;
        t = 3 + (w >> 10);
        eb = (size_t)(w & 1023) * 1024;
        dst = g_hiW + (size_t)(t - 3) * NW;
    }
    const size_t i = eb + (size_t)threadIdx.x * 4;
    float4 v = *(const float4*)(p.s[t] + i);
    *(uint2*)(dst + i) = make_uint2(pack_h2(v.x, v.y), pack_h2(v.z, v.w));
}

// ---------------------------------------------------------------------------
// mma.sync fp16 1-term GEMM (unchanged from R14, proven 128 regs / 2 blocks)
// ---------------------------------------------------------------------------
template <bool SPLIT>
__device__ __forceinline__ void gemm_mma_core(
    const __half* __restrict__ Ahi, const __half* __restrict__ Whi,
    const float* __restrict__ bias, float* __restrict__ Cf,
    __half* __restrict__ Chi)
{
    constexpr int W_OFF = 8192;
    constexpr int BUFSZ = 16384;
    __shared__ char smbuf[2 * BUFSZ];
    const int tid = threadIdx.x, lane = tid & 31, wid = tid >> 5;
    const int warpM = wid & 3, warpN = wid >> 2;
    const int row0 = blockIdx.y * 128, col0 = blockIdx.x * 128;
    const uint32_t sb = smem_u32(smbuf);

    const int grow = tid >> 2, gch = tid & 3;
    const size_t aoff0 = (size_t)(row0 + grow) * (DMODEL * 2) + gch * 16;
    const size_t aoff1 = aoff0 + (size_t)64 * (DMODEL * 2);
    const size_t woff0 = (size_t)(col0 + grow) * (DMODEL * 2) + gch * 16;
    const size_t woff1 = woff0 + (size_t)64 * (DMODEL * 2);
    const uint32_t d0 = SWB(grow, gch);
    const uint32_t d1 = SWB(grow + 64, gch);

    float acc[2][8][4];
#pragma unroll
    for (int mt = 0; mt < 2; mt++)
#pragma unroll
        for (int nt = 0; nt < 8; nt++)
#pragma unroll
            for (int e = 0; e < 4; e++) acc[mt][nt][e] = 0.f;

    uint4 pre[4];
    pre[0] = *(const uint4*)((const char*)Ahi + aoff0);
    pre[1] = *(const uint4*)((const char*)Ahi + aoff1);
    pre[2] = *(const uint4*)((const char*)Whi + woff0);
    pre[3] = *(const uint4*)((const char*)Whi + woff1);

    const int arowl = warpM * 32 + (lane & 7) + ((lane >> 3) & 1) * 8;
    const int achl  = (lane >> 4) & 1;
    const int brow8 = (lane & 7) + ((lane >> 4) & 1) * 8;
    const int bchl  = (lane >> 3) & 1;

    int buf = 0;
    for (int c = 0; c < 32; c++) {
        char* base = smbuf + buf * BUFSZ;
        *(uint4*)(base + 0     + d0) = pre[0];
        *(uint4*)(base + 0     + d1) = pre[1];
        *(uint4*)(base + W_OFF + d0) = pre[2];
        *(uint4*)(base + W_OFF + d1) = pre[3];
        __syncthreads();

        if (c + 1 < 32) {
            const size_t cb = (size_t)(c + 1) * 64;
            pre[0] = *(const uint4*)((const char*)Ahi + aoff0 + cb);
            pre[1] = *(const uint4*)((const char*)Ahi + aoff1 + cb);
            pre[2] = *(const uint4*)((const char*)Whi + woff0 + cb);
            pre[3] = *(const uint4*)((const char*)Whi + woff1 + cb);
        }

        const uint32_t bb = sb + buf * BUFSZ;
#pragma unroll
        for (int ks = 0; ks < 2; ks++) {
            uint32_t a_hi[2][4];
#pragma unroll
            for (int mt = 0; mt < 2; mt++)
                ldsm4(a_hi[mt], bb + SWB(arowl + mt * 16, ks * 2 + achl));
#pragma unroll
            for (int np = 0; np < 4; np++) {
                uint32_t bh4[4];
                ldsm4(bh4, bb + W_OFF + SWB(warpN * 64 + np * 16 + brow8, ks * 2 + bchl));
#pragma unroll
                for (int mt = 0; mt < 2; mt++) {
                    mma_f16(acc[mt][np * 2 + 0], a_hi[mt], &bh4[0]);
                    mma_f16(acc[mt][np * 2 + 1], a_hi[mt], &bh4[2]);
                }
            }
        }
        buf ^= 1;
    }

#pragma unroll
    for (int mt = 0; mt < 2; mt++) {
        const int r = row0 + warpM * 32 + mt * 16 + (lane >> 2);
#pragma unroll
        for (int nt = 0; nt < 8; nt++) {
            const int col = col0 + warpN * 64 + nt * 8 + (lane & 3) * 2;
            const float b0 = bias[col], b1 = bias[col + 1];
            const float o0 = acc[mt][nt][0] + b0, o1 = acc[mt][nt][1] + b1;
            const float o2 = acc[mt][nt][2] + b0, o3 = acc[mt][nt][3] + b1;
            if (SPLIT) {
                *(uint32_t*)&Chi[(size_t)r * DMODEL + col]       = pack_h2(o0, o1);
                *(uint32_t*)&Chi[(size_t)(r + 8) * DMODEL + col] = pack_h2(o2, o3);
            } else {
                *(float2*)&Cf[(size_t)r * DMODEL + col]       = make_float2(o0, o1);
                *(float2*)&Cf[(size_t)(r + 8) * DMODEL + col] = make_float2(o2, o3);
            }
        }
    }
}

__global__ void __launch_bounds__(256, 2) qkv_mma(
    const float* __restrict__ bq, const float* __restrict__ bk, const float* __restrict__ bv)
{
    const int z = blockIdx.z;
    const float* bias = (z == 0) ? bq : (z == 1) ? bk : bv;
    gemm_mma_core<true>(g_hiX + z * NX, g_hiW + z * NW, bias, nullptr, g_hiQKV + z * NX);
}

__global__ void __launch_bounds__(256, 2) out_mma(
    const float* __restrict__ bo, float* __restrict__ C)
{
    gemm_mma_core<false>(g_hiC, g_hiW + 3 * NW, bo, C, nullptr);
}

// ---------------------------------------------------------------------------
// Fused single-pass attention: QK^T -> exp -> rowsum (warp-local) ->
// expS frags to scratch (coalesced uint4 layout) -> PV on UNNORMALIZED expS
// -> ctx * rinv at the end.  Each warp owns 16 full S-rows (no cross-warp
// reductions).  K/V double-buffered, 1 sync per chunk.
// Smem: Q 16K | Kbuf 2x8K | Vbuf 2x8K = 48KB
// ---------------------------------------------------------------------------
#define ATT_SMEM 49152

__global__ void __launch_bounds__(256, 2) attn_fused()
{
    extern __shared__ char sm[];
    const uint32_t sQh = smem_u32(sm);

    const int tid = threadIdx.x, lane = tid & 31, wid = tid >> 5;
    const int p = blockIdx.y, bb = p >> 4, h = p & 15;
    const int row0 = blockIdx.x * 128;
    uint4* const sbase = (uint4*)g_expS + (size_t)(p * 16 + blockIdx.x) * 32768;

    // per-thread staging coords (2 passes of 256 threads over 64x64 tiles)
    const int srow0 = tid >> 3,         sch0 = tid & 7;
    const int srow1 = (tid + 256) >> 3, sch1 = (tid + 256) & 7;
    const uint32_t sso0 = SWB128(srow0, sch0);
    const uint32_t sso1 = SWB128(srow1, sch1);

    // stage Q tile (128 x 64)
#pragma unroll
    for (int ps = 0; ps < 4; ps++) {
        const int u = tid + ps * 256;
        const int row = u >> 3, ch = u & 7;
        const size_t ge = (size_t)(bb * S_LEN + row0 + row) * DMODEL + h * HDIM + ch * 8;
        *(uint4*)(sm + SWB128(row, ch)) = *(const uint4*)(g_hiQKV + ge);
    }
    // stage K,V chunk 0 into buf0
    {
        const size_t kg0 = NX     + (size_t)(bb * S_LEN + srow0) * DMODEL + h * HDIM + sch0 * 8;
        const size_t kg1 = NX     + (size_t)(bb * S_LEN + srow1) * DMODEL + h * HDIM + sch1 * 8;
        const size_t vg0 = 2 * NX + (size_t)(bb * S_LEN + srow0) * DMODEL + h * HDIM + sch0 * 8;
        const size_t vg1 = 2 * NX + (size_t)(bb * S_LEN + srow1) * DMODEL + h * HDIM + sch1 * 8;
        *(uint4*)(sm + 16384 + sso0) = *(const uint4*)(g_hiQKV + kg0);
        *(uint4*)(sm + 16384 + sso1) = *(const uint4*)(g_hiQKV + kg1);
        *(uint4*)(sm + 32768 + sso0) = *(const uint4*)(g_hiQKV + vg0);
        *(uint4*)(sm + 32768 + sso1) = *(const uint4*)(g_hiQKV + vg1);
    }
    __syncthreads();

    // fragment lane addressing: warp owns S rows [wid*16, wid*16+16)
    const int arowl = wid * 16 + (lane & 7) + ((lane >> 3) & 1) * 8;
    const int achl  = (lane >> 4) & 1;
    const int brow8 = (lane & 7) + ((lane >> 4) & 1) * 8;
    const int bchl  = (lane >> 3) & 1;
    const int vrowl = (lane & 7) + ((lane >> 3) & 1) * 8;
    const int vtog  = (lane >> 4) & 1;
    const float sc = 0.125f;

    float ctx[8][4];
#pragma unroll
    for (int nt = 0; nt < 8; nt++)
#pragma unroll
        for (int e = 0; e < 4; e++) ctx[nt][e] = 0.f;
    float rs0 = 0.f, rs1 = 0.f;

    for (int c = 0; c < 32; c++) {
        // prefetch K,V chunk c+1 (overlaps all compute below)
        uint4 k0, k1, v0, v1;
        if (c + 1 < 32) {
            const int c1 = (c + 1) * 64;
            k0 = *(const uint4*)(g_hiQKV + NX     + (size_t)(bb * S_LEN + c1 + srow0) * DMODEL + h * HDIM + sch0 * 8);
            k1 = *(const uint4*)(g_hiQKV + NX     + (size_t)(bb * S_LEN + c1 + srow1) * DMODEL + h * HDIM + sch1 * 8);
            v0 = *(const uint4*)(g_hiQKV + 2 * NX + (size_t)(bb * S_LEN + c1 + srow0) * DMODEL + h * HDIM + sch0 * 8);
            v1 = *(const uint4*)(g_hiQKV + 2 * NX + (size_t)(bb * S_LEN + c1 + srow1) * DMODEL + h * HDIM + sch1 * 8);
        }
        const uint32_t kcur = sQh + 16384 + (c & 1) * 8192;
        const uint32_t vcur = sQh + 32768 + (c & 1) * 8192;

        // ---- QK^T: 16 rows x 64 keys per warp ----
        float acc[8][4];
#pragma unroll
        for (int nt = 0; nt < 8; nt++)
#pragma unroll
            for (int e = 0; e < 4; e++) acc[nt][e] = 0.f;
#pragma unroll
        for (int ks = 0; ks < 4; ks++) {
            uint32_t a4[4];
            ldsm4(a4, sQh + SWB128(arowl, ks * 2 + achl));
#pragma unroll
            for (int np = 0; np < 4; np++) {
                uint32_t bh4[4];
                ldsm4(bh4, kcur + SWB128(np * 16 + brow8, ks * 2 + bchl));
                mma_f16(acc[np * 2 + 0], a4, &bh4[0]);
                mma_f16(acc[np * 2 + 1], a4, &bh4[2]);
            }
        }

        // ---- exp, rowsums, pack fragments ----
        uint32_t frag[16];
#pragma unroll
        for (int nt = 0; nt < 8; nt++) {
            const float e0 = __expf(acc[nt][0] * sc);
            const float e1 = __expf(acc[nt][1] * sc);
            const float e2 = __expf(acc[nt][2] * sc);
            const float e3 = __expf(acc[nt][3] * sc);
            rs0 += e0 + e1;
            rs1 += e2 + e3;
            frag[nt * 2 + 0] = pack_h2(e0, e1);
            frag[nt * 2 + 1] = pack_h2(e2, e3);
        }
        // scratch store (coalesced: consecutive tids -> consecutive uint4)
        uint4* sp = sbase + (size_t)c * 1024 + tid;
#pragma unroll
        for (int j = 0; j < 4; j++)
            sp[j * 256] = *(uint4*)(frag + j * 4);

        // store prefetched K/V into the other buffer
        if (c + 1 < 32) {
            char* kb = sm + 16384 + ((c + 1) & 1) * 8192;
            char* vb = sm + 32768 + ((c + 1) & 1) * 8192;
            *(uint4*)(kb + sso0) = k0;
            *(uint4*)(kb + sso1) = k1;
            *(uint4*)(vb + sso0) = v0;
            *(uint4*)(vb + sso1) = v1;
        }

        // ---- PV on unnormalized expS: ctx[16 rows][64 hd] ----
#pragma unroll
        for (int kg = 0; kg < 4; kg++) {
            const uint32_t* ah = frag + kg * 4;
#pragma unroll
            for (int ld = 0; ld < 4; ld++) {
                uint32_t bh4[4];
                ldsm4t(bh4, vcur + SWB128(kg * 16 + vrowl, ld * 2 + vtog));
                mma_f16(ctx[ld * 2 + 0], ah, &bh4[0]);
                mma_f16(ctx[ld * 2 + 1], ah, &bh4[2]);
            }
        }
        __syncthreads();
    }

    // ---- warp-local rowsum reduce + rinv + scaled ctx write ----
    rs0 += __shfl_xor_sync(0xffffffffu, rs0, 1);
    rs0 += __shfl_xor_sync(0xffffffffu, rs0, 2);
    rs1 += __shfl_xor_sync(0xffffffffu, rs1, 1);
    rs1 += __shfl_xor_sync(0xffffffffu, rs1, 2);
    const float rinv0 = 1.0f / rs0;
    const float rinv1 = 1.0f / rs1;
    const int r0 = wid * 16 + (lane >> 2);
    if ((lane & 3) == 0) {
        g_rowinv[p * S_LEN + row0 + r0]     = rinv0;
        g_rowinv[p * S_LEN + row0 + r0 + 8] = rinv1;
    }
    const size_t gr0 = (size_t)(bb * S_LEN + row0 + r0) * DMODEL + h * HDIM;
    const size_t gr1 = gr0 + (size_t)8 * DMODEL;
#pragma unroll
    for (int nt = 0; nt < 8; nt++) {
        const int col = nt * 8 + (lane & 3) * 2;
        *(uint32_t*)&g_hiC[gr0 + col] = pack_h2(ctx[nt][0] * rinv0, ctx[nt][1] * rinv0);
        *(uint32_t*)&g_hiC[gr1 + col] = pack_h2(ctx[nt][2] * rinv1, ctx[nt][3] * rinv1);
    }
}

// ---------------------------------------------------------------------------
// Streaming normalize: read expS frags (coalesced), scale by rinv, write fp32
// attn. No smem, no syncs. grid = (512 tiles, 4 chunk-groups).
// ---------------------------------------------------------------------------
__global__ void __launch_bounds__(256) norm_attn(float* __restrict__ attn)
{
    const int bx = blockIdx.x;            // 0..511 : (p*16 + rowblock)
    const int p = bx >> 4, rb = bx & 15;
    const int row0 = rb * 128;
    const int tid = threadIdx.x, lane = tid & 31, wid = tid >> 5;
    const uint4* const sbase = (const uint4*)g_expS + (size_t)bx * 32768;

    const int r0 = wid * 16 + (lane >> 2);
    const __half2 h0 = __float2half2_rn(g_rowinv[p * S_LEN + row0 + r0]);
    const __half2 h1 = __float2half2_rn(g_rowinv[p * S_LEN + row0 + r0 + 8]);
    const size_t ga0 = ((size_t)(p * S_LEN) + row0 + r0) * S_LEN;
    const size_t ga1 = ga0 + (size_t)8 * S_LEN;

    const int cbeg = blockIdx.y * 8, cend = cbeg + 8;
    for (int c = cbeg; c < cend; c++) {
        uint32_t frag[16];
        const uint4* sp = sbase + (size_t)c * 1024 + tid;
#pragma unroll
        for (int j = 0; j < 4; j++)
            *(uint4*)(frag + j * 4) = sp[j * 256];
        const int c0 = c * 64;
#pragma unroll
        for (int nt = 0; nt < 8; nt++) {
            const int col = c0 + nt * 8 + (lane & 3) * 2;
            __half2 s0 = __hmul2(*(__half2*)&frag[nt * 2 + 0], h0);
            __half2 s1 = __hmul2(*(__half2*)&frag[nt * 2 + 1], h1);
            *(float2*)&attn[ga0 + col] = __half22float2(s0);
            *(float2*)&attn[ga1 + col] = __half22float2(s1);
        }
    }
}

// ---------------------------------------------------------------------------
extern "C" void kernel_launch(void* const* d_in, const int* in_sizes, int n_in,
                              void* d_out, int out_size) {
    const float* query = (const float*)d_in[0];
    const float* key_  = (const float*)d_in[1];
    const float* value = (const float*)d_in[2];
    const float* Wq = (const float*)d_in[3];
    const float* bq = (const float*)d_in[4];
    const float* Wk = (const float*)d_in[5];
    const float* bk = (const float*)d_in[6];
    const float* Wv = (const float*)d_in[7];
    const float* bv = (const float*)d_in[8];
    const float* Wo = (const float*)d_in[9];
    const float* bo = (const float*)d_in[10];

    float* outp = (float*)d_out;
    float* attn = outp + NX;          // tuple output: (out, attn)

    static int attr_set = 0;
    if (!attr_set) {
        cudaFuncSetAttribute(attn_fused, cudaFuncAttributeMaxDynamicSharedMemorySize, ATT_SMEM);
        attr_set = 1;
    }

    ConvSrcs cs;
    cs.s[0] = query; cs.s[1] = key_; cs.s[2] = value;
    cs.s[3] = Wq; cs.s[4] = Wk; cs.s[5] = Wv; cs.s[6] = Wo;
    conv_all<<<16384, 256>>>(cs);

    qkv_mma<<<dim3(DMODEL / 128, MROWS / 128, 3), 256>>>(bq, bk, bv);
    attn_fused<<<dim3(S_LEN / 128, NPAIRS), 256, ATT_SMEM>>>();
    out_mma<<<dim3(DMODEL / 128, MROWS / 128), 256>>>(bo, outp);
    norm_attn<<<dim3(512, 4), 256>>>(attn);
}